// round 9
// baseline (speedup 1.0000x reference)
#include <cuda_runtime.h>
#include <cuda_bf16.h>
#include <math.h>
#include <stdint.h>

#define BTOT 32768
#define NDM 256
#define NDI 256
#define NDS 16
#define NFF 512

// ---- scratch (static device globals; no allocation) ----
__device__ float g_u[(size_t)BTOT*NDI];
__device__ float g_gate[(size_t)BTOT*NDI];
__device__ float g_delta[(size_t)BTOT*NDI];
__device__ float g_Bm[(size_t)BTOT*NDS];
__device__ float g_Cm[(size_t)BTOT*NDS];
__device__ float g_y[(size_t)BTOT*NDI];
__device__ float g_s[(size_t)BTOT*NDM];
__device__ float g_negA[NDI*NDS];
__device__ int   g_powok;

// packed split-bf16 activations: row = [hi(0..K-1) | lo(0..K-1)]
__device__ __nv_bfloat16 g_pospk[(size_t)BTOT*512];   // K=256
__device__ __nv_bfloat16 g_ypk[(size_t)BTOT*512];     // K=256
__device__ __nv_bfloat16 g_tpk[(size_t)BTOT*1024];    // K=512
// packed split-bf16 weights: row n = [hi(0..K-1) | lo(0..K-1)]
__device__ __nv_bfloat16 g_W0pk[512*512];
__device__ __nv_bfloat16 g_W1pk[512*512];
__device__ __nv_bfloat16 g_W2pk[256*1024];

__device__ __forceinline__ float siluf(float x) { return x / (1.f + __expf(-x)); }

__device__ __forceinline__ void packsplit(float v, __nv_bfloat16* hi_p, __nv_bfloat16* lo_p) {
    __nv_bfloat16 hi = __float2bfloat16(v);
    *hi_p = hi;
    *lo_p = __float2bfloat16(v - __bfloat162float(hi));
}

// ---------------- K0a: flag reset + precompute -exp(A_log), verify power pattern ----------------
__global__ void k_flagset() { g_powok = 1; }
__global__ void k_prep(const float* __restrict__ A_log) {
    int i = blockIdx.x * 256 + threadIdx.x;
    float v = -expf(A_log[i]);
    g_negA[i] = v;
    int s = i & 15;
    float expect = -(float)(s + 1);
    if (fabsf(v - expect) > 1e-3f * (float)(s + 1)) atomicExch(&g_powok, 0);
}

// ---------------- K0b: pack weights to split bf16 ----------------
__global__ void k_packw(const float* __restrict__ W, int K, int sel) {
    int i = blockIdx.x * 256 + threadIdx.x;    // over rows*K
    int n = i / K, k = i - n * K;
    __nv_bfloat16* dst = sel == 0 ? g_W0pk : (sel == 1 ? g_W1pk : g_W2pk);
    float v = W[i];
    __nv_bfloat16 hi = __float2bfloat16(v);
    dst[(size_t)n * 2 * K + k] = hi;
    dst[(size_t)n * 2 * K + K + k] = __float2bfloat16(v - __bfloat162float(hi));
}

// ---------------- K1: sine embedding (writes packed bf16 split) ----------------
__global__ void __launch_bounds__(256) k_embed(const float* __restrict__ x0) {
    int idx = blockIdx.x * 256 + threadIdx.x;        // over BTOT*256
    int b = idx >> 8;
    int c = idx & 255;
    int a = c >> 6;
    int w = c & 63;
    int j = w >> 1;
    float v = x0[b * 4 + a];
    float freq_inv = __expf(-(float)j * 0.28782313662425576f); // ln(10000)/32
    float p = v * 6.283185307179586f * freq_inv;
    float val = (w & 1) ? __cosf(p) : __sinf(p);
    packsplit(val, &g_pospk[(size_t)b * 512 + c], &g_pospk[(size_t)b * 512 + 256 + c]);
}

// ================= HMMA (mma.sync bf16) split-bf16 GEMM, cp.async pipelined =================
__device__ __forceinline__ void ldsm_x4(uint32_t* a, uint32_t addr) {
    asm volatile("ldmatrix.sync.aligned.m8n8.x4.shared.b16 {%0,%1,%2,%3}, [%4];"
                 : "=r"(a[0]), "=r"(a[1]), "=r"(a[2]), "=r"(a[3]) : "r"(addr));
}
__device__ __forceinline__ void ldsm_x2(uint32_t* b, uint32_t addr) {
    asm volatile("ldmatrix.sync.aligned.m8n8.x2.shared.b16 {%0,%1}, [%2];"
                 : "=r"(b[0]), "=r"(b[1]) : "r"(addr));
}
__device__ __forceinline__ void mma16816(float* d, const uint32_t* a, const uint32_t* b) {
    asm volatile(
        "mma.sync.aligned.m16n8k16.row.col.f32.bf16.bf16.f32 "
        "{%0,%1,%2,%3}, {%4,%5,%6,%7}, {%8,%9}, {%0,%1,%2,%3};"
        : "+f"(d[0]), "+f"(d[1]), "+f"(d[2]), "+f"(d[3])
        : "r"(a[0]), "r"(a[1]), "r"(a[2]), "r"(a[3]), "r"(b[0]), "r"(b[1]));
}
__device__ __forceinline__ void cp16(uint32_t smem, const void* gmem) {
    asm volatile("cp.async.cg.shared.global [%0], [%1], 16;"
                 :: "r"(smem), "l"(gmem));
}
__device__ __forceinline__ void cp_commit() {
    asm volatile("cp.async.commit_group;");
}
template <int N>
__device__ __forceinline__ void cp_wait() {
    asm volatile("cp.async.wait_group %0;" :: "n"(N));
}

template <int KDIM, int NOUT, int MODE>
__global__ void __launch_bounds__(256) k_hgemm(const float* __restrict__ bias) {
    extern __shared__ char smem_raw[];
    const __nv_bfloat16* __restrict__ Apk =
        MODE == 0 ? g_pospk : (MODE == 1 ? g_ypk : g_tpk);
    const __nv_bfloat16* __restrict__ Wpk =
        MODE == 0 ? g_W0pk : (MODE == 1 ? g_W1pk : g_W2pk);

    constexpr int KD2 = 2 * KDIM;
    constexpr int KCH = KDIM / 64;      // 64-col chunks per pass
    constexpr int NCH = 3 * KCH;        // total chunks over 3 passes
    constexpr int STG = 32768;          // stage size: 16KB A + 16KB B

    const int tid = threadIdx.x;
    const int wid = tid >> 5;
    const int lane = tid & 31;
    const int wm = wid & 1;
    const int wn = wid >> 1;
    const int m0 = blockIdx.y * 128;
    const int n0 = blockIdx.x * 128;
    uint32_t sb = (uint32_t)__cvta_generic_to_shared(smem_raw);
    sb = (sb + 127u) & ~127u;

    const int sr = tid >> 3;
    const int sc = tid & 7;
    const uint32_t soff = (uint32_t)(((sc ^ (sr & 7)) * 16));

    auto stage = [&](int c, int buf) {
        int pass = c / KCH;
        int kc = (c - pass * KCH) * 64;
        int acol = (pass == 2 ? KDIM : 0) + kc;
        int bcol = (pass == 1 ? KDIM : 0) + kc;
        uint32_t abase = sb + buf * STG;
        uint32_t bbase = abase + 16384;
        const __nv_bfloat16* ag = Apk + (size_t)(m0 + sr) * KD2 + acol + sc * 8;
        const __nv_bfloat16* wg = Wpk + (size_t)(n0 + sr) * KD2 + bcol + sc * 8;
#pragma unroll
        for (int i = 0; i < 4; i++) {
            int r = sr + i * 32;
            cp16(abase + r * 128 + soff, ag + (size_t)i * 32 * KD2);
            cp16(bbase + r * 128 + soff, wg + (size_t)i * 32 * KD2);
        }
    };

    float acc[4][4][4];
#pragma unroll
    for (int i = 0; i < 4; i++)
#pragma unroll
        for (int j = 0; j < 4; j++)
#pragma unroll
            for (int q = 0; q < 4; q++) acc[i][j][q] = 0.f;

    stage(0, 0);
    cp_commit();

#pragma unroll 1
    for (int c = 0; c < NCH; c++) {
        if (c + 1 < NCH) {
            stage(c + 1, (c + 1) & 1);
            cp_commit();
            cp_wait<1>();
        } else {
            cp_wait<0>();
        }
        __syncthreads();
        uint32_t sAb = sb + (c & 1) * STG;
        uint32_t sBb = sAb + 16384;
#pragma unroll
        for (int ks = 0; ks < 4; ks++) {
            uint32_t afr[4][4], bfr[4][2];
#pragma unroll
            for (int i = 0; i < 4; i++) {
                int r = wm * 64 + i * 16 + (lane & 15);
                int cc = ks * 2 + (lane >> 4);
                ldsm_x4(afr[i], sAb + r * 128 + ((cc ^ (r & 7)) * 16));
            }
#pragma unroll
            for (int j = 0; j < 4; j++) {
                int r = wn * 32 + j * 8 + (lane & 7);
                int cc = ks * 2 + ((lane >> 3) & 1);
                ldsm_x2(bfr[j], sBb + r * 128 + ((cc ^ (r & 7)) * 16));
            }
#pragma unroll
            for (int i = 0; i < 4; i++)
#pragma unroll
                for (int j = 0; j < 4; j++) mma16816(acc[i][j], afr[i], bfr[j]);
        }
        __syncthreads();
    }

    const int g = lane >> 2;
    const int t2 = (lane & 3) * 2;
#pragma unroll
    for (int i = 0; i < 4; i++) {
#pragma unroll
        for (int j = 0; j < 4; j++) {
#pragma unroll
            for (int h = 0; h < 2; h++) {
                int m = m0 + wm * 64 + i * 16 + g + h * 8;
                int nb = n0 + wn * 32 + j * 8 + t2;
#pragma unroll
                for (int e = 0; e < 2; e++) {
                    int n = nb + e;
                    float v = acc[i][j][h * 2 + e];
                    if (MODE == 0) {
                        if (n < 256) g_u[(size_t)m * 256 + n] = siluf(v);
                        else         g_gate[(size_t)m * 256 + n - 256] = v;
                    } else if (MODE == 1) {
                        float t = fmaxf(v + __ldg(&bias[n]), 0.f);
                        packsplit(t, &g_tpk[(size_t)m * 1024 + n],
                                     &g_tpk[(size_t)m * 1024 + 512 + n]);
                    } else {
                        g_s[(size_t)m * 256 + n] =
                            v + __ldg(&bias[n]) + g_y[(size_t)m * 256 + n];
                    }
                }
            }
        }
    }
}

// ---------------- K3: x_dbl = flow @ W_x^T (register-tiled) + delta ----------------
// 64 rows per block, 48 cols; thread = (rowgrp 0..15)x(colgrp 0..15) -> 4 rows x 3 cols
__global__ void __launch_bounds__(256) k_xdbl(const float* __restrict__ flow,
                                              const float* __restrict__ W_x,
                                              const float* __restrict__ W_dt,
                                              const float* __restrict__ b_dt) {
    extern __shared__ float sx[];
    float* sW = sx;                       // [48][257]
    float* sF = sW + 48 * 257;            // [64][257]
    float* sdlt = sF + 64 * 257;          // [64][17]
    const int b0 = blockIdx.x * 64;
    const int tid = threadIdx.x;

    for (int i = tid; i < 48 * 64; i += 256) {
        int r = i >> 6;
        int c4 = (i & 63) << 2;
        float4 v = __ldg((const float4*)(W_x + (size_t)r * 256 + c4));
        float* d = sW + r * 257 + c4;
        d[0] = v.x; d[1] = v.y; d[2] = v.z; d[3] = v.w;
    }
    for (int i = tid; i < 64 * 64; i += 256) {
        int r = i >> 6;
        int c4 = (i & 63) << 2;
        float4 v = *(const float4*)(flow + (size_t)(b0 + r) * 256 + c4);
        float* d = sF + r * 257 + c4;
        d[0] = v.x; d[1] = v.y; d[2] = v.z; d[3] = v.w;
    }
    __syncthreads();

    {
        const int rg = (tid >> 4) * 4;     // 4 rows
        const int cg = (tid & 15) * 3;     // 3 cols
        const float* w0 = sW + (cg + 0) * 257;
        const float* w1 = sW + (cg + 1) * 257;
        const float* w2 = sW + (cg + 2) * 257;
        const float* f0 = sF + (rg + 0) * 257;
        const float* f1 = sF + (rg + 1) * 257;
        const float* f2 = sF + (rg + 2) * 257;
        const float* f3 = sF + (rg + 3) * 257;
        float acc[4][3];
#pragma unroll
        for (int i = 0; i < 4; i++)
#pragma unroll
            for (int j = 0; j < 3; j++) acc[i][j] = 0.f;
#pragma unroll 8
        for (int k = 0; k < 256; k++) {
            float a = w0[k], b = w1[k], c = w2[k];
            float x0v = f0[k], x1v = f1[k], x2v = f2[k], x3v = f3[k];
            acc[0][0] = fmaf(x0v, a, acc[0][0]);
            acc[0][1] = fmaf(x0v, b, acc[0][1]);
            acc[0][2] = fmaf(x0v, c, acc[0][2]);
            acc[1][0] = fmaf(x1v, a, acc[1][0]);
            acc[1][1] = fmaf(x1v, b, acc[1][1]);
            acc[1][2] = fmaf(x1v, c, acc[1][2]);
            acc[2][0] = fmaf(x2v, a, acc[2][0]);
            acc[2][1] = fmaf(x2v, b, acc[2][1]);
            acc[2][2] = fmaf(x2v, c, acc[2][2]);
            acc[3][0] = fmaf(x3v, a, acc[3][0]);
            acc[3][1] = fmaf(x3v, b, acc[3][1]);
            acc[3][2] = fmaf(x3v, c, acc[3][2]);
        }
#pragma unroll
        for (int i = 0; i < 4; i++) {
            int row = rg + i;
            int b = b0 + row;
#pragma unroll
            for (int j = 0; j < 3; j++) {
                int c = cg + j;
                float s = acc[i][j];
                if (c < 16)       sdlt[row * 17 + c] = s;
                else if (c < 32)  g_Bm[(size_t)b * 16 + c - 16] = s;
                else              g_Cm[(size_t)b * 16 + c - 32] = s;
            }
        }
    }
    __syncthreads();

    const int d = tid;
    float4 wd0 = __ldg((const float4*)(W_dt + d * 16));
    float4 wd1 = __ldg((const float4*)(W_dt + d * 16 + 4));
    float4 wd2 = __ldg((const float4*)(W_dt + d * 16 + 8));
    float4 wd3 = __ldg((const float4*)(W_dt + d * 16 + 12));
    float bd = __ldg(&b_dt[d]);
#pragma unroll 4
    for (int row = 0; row < 64; row++) {
        const float* dl = sdlt + row * 17;
        float s = bd;
        s += wd0.x * dl[0]  + wd0.y * dl[1]  + wd0.z * dl[2]  + wd0.w * dl[3];
        s += wd1.x * dl[4]  + wd1.y * dl[5]  + wd1.z * dl[6]  + wd1.w * dl[7];
        s += wd2.x * dl[8]  + wd2.y * dl[9]  + wd2.z * dl[10] + wd2.w * dl[11];
        s += wd3.x * dl[12] + wd3.y * dl[13] + wd3.z * dl[14] + wd3.w * dl[15];
        g_delta[(size_t)(b0 + row) * 256 + d] = log1pf(expf(s));
    }
}

// ---------------- K4: SSM state update, one block per b, coalesced float4 map ----------------
// thread t handles float4 indices {t, t+256, t+512, t+768} of the 1024 float4s of row b:
// index i -> (d = i>>2, q = i&3). Warp lanes hit consecutive float4s -> 4 lines/LDG.
__global__ void __launch_bounds__(256) k_mamba(const float* __restrict__ h,
                                               const float* __restrict__ Dv,
                                               float* __restrict__ h_new) {
    const int b = blockIdx.x;
    const int t = threadIdx.x;
    const int q = t & 3;
    const int d0 = t >> 2;          // 0..63
    __shared__ float sB[16], sC[16];
    if (t < 16)       sB[t] = g_Bm[(size_t)b * 16 + t];
    else if (t < 32)  sC[t - 16] = g_Cm[(size_t)b * 16 + t - 16];
    __syncthreads();

    const float B0 = sB[q * 4 + 0], B1 = sB[q * 4 + 1],
                B2 = sB[q * 4 + 2], B3 = sB[q * 4 + 3];
    const float C0 = sC[q * 4 + 0], C1 = sC[q * 4 + 1],
                C2 = sC[q * 4 + 2], C3 = sC[q * 4 + 3];
    const float4* hp = (const float4*)(h + (size_t)b * 4096);
    float4* op = (float4*)(h_new + (size_t)b * 4096);
    const size_t rbase = (size_t)b * 256;
    const bool powok = (g_powok != 0);

#pragma unroll
    for (int j = 0; j < 4; j++) {
        const int d = d0 + 64 * j;
        const size_t base = rbase + d;
        const float delta = g_delta[base];
        const float u = g_u[base];
        const float du = delta * u;
        float4 hv = __ldcs(&hp[t + 256 * j]);
        float4 o;
        if (powok) {
            // deltaA[s] = r^(s+1); this thread covers s = 4q..4q+3
            float r = __expf(-delta);
            float r2 = r * r;
            float r4 = r2 * r2;
            float p = r;                    // r^1
            if (q & 1) p *= r4;
            if (q & 2) p *= r4 * r4;        // p = r^(4q+1)
            o.x = p * hv.x + du * B0; p *= r;
            o.y = p * hv.y + du * B1; p *= r;
            o.z = p * hv.z + du * B2; p *= r;
            o.w = p * hv.w + du * B3;
        } else {
            float4 al = __ldg((const float4*)(g_negA + d * 16 + q * 4));
            o.x = __expf(al.x * delta) * hv.x + du * B0;
            o.y = __expf(al.y * delta) * hv.y + du * B1;
            o.z = __expf(al.z * delta) * hv.z + du * B2;
            o.w = __expf(al.w * delta) * hv.w + du * B3;
        }
        __stcs(&op[t + 256 * j], o);

        float y = o.x * C0 + o.y * C1 + o.z * C2 + o.w * C3;
        y += __shfl_xor_sync(0xffffffffu, y, 1);
        y += __shfl_xor_sync(0xffffffffu, y, 2);
        if (q == 0) {
            y += u * __ldg(&Dv[d]);
            float g = g_gate[base];
            float yv = y * siluf(g);
            g_y[base] = yv;
            packsplit(yv, &g_ypk[(size_t)b * 512 + d],
                          &g_ypk[(size_t)b * 512 + 256 + d]);
        }
    }
}

// ---------------- K7: LayerNorm + 4-way head + sigmoid; warp per row ----------------
__global__ void __launch_bounds__(256) k_head(const float* __restrict__ gamma,
                                              const float* __restrict__ beta,
                                              const float* __restrict__ W_bb,
                                              const float* __restrict__ b_bb,
                                              float* __restrict__ out) {
    int warp = threadIdx.x >> 5;
    int lane = threadIdx.x & 31;
    int b = blockIdx.x * 8 + warp;
    const float* srow = g_s + (size_t)b * 256;

    float v[8];
    float sum = 0.f;
#pragma unroll
    for (int i = 0; i < 8; i++) { v[i] = srow[i * 32 + lane]; sum += v[i]; }
#pragma unroll
    for (int o = 16; o > 0; o >>= 1) sum += __shfl_xor_sync(0xffffffffu, sum, o);
    float mu = sum * (1.f / 256.f);
    float sq = 0.f;
#pragma unroll
    for (int i = 0; i < 8; i++) { float dd = v[i] - mu; sq += dd * dd; }
#pragma unroll
    for (int o = 16; o > 0; o >>= 1) sq += __shfl_xor_sync(0xffffffffu, sq, o);
    float inv = rsqrtf(sq * (1.f / 256.f) + 1e-5f);

    float a0 = 0.f, a1 = 0.f, a2 = 0.f, a3 = 0.f;
#pragma unroll
    for (int i = 0; i < 8; i++) {
        int c = i * 32 + lane;
        float sn = (v[i] - mu) * inv * __ldg(&gamma[c]) + __ldg(&beta[c]);
        a0 += sn * __ldg(&W_bb[c]);
        a1 += sn * __ldg(&W_bb[256 + c]);
        a2 += sn * __ldg(&W_bb[512 + c]);
        a3 += sn * __ldg(&W_bb[768 + c]);
    }
#pragma unroll
    for (int o = 16; o > 0; o >>= 1) {
        a0 += __shfl_xor_sync(0xffffffffu, a0, o);
        a1 += __shfl_xor_sync(0xffffffffu, a1, o);
        a2 += __shfl_xor_sync(0xffffffffu, a2, o);
        a3 += __shfl_xor_sync(0xffffffffu, a3, o);
    }
    if (lane == 0) {
        out[b * 4 + 0] = 1.f / (1.f + expf(-(a0 + __ldg(&b_bb[0]))));
        out[b * 4 + 1] = 1.f / (1.f + expf(-(a1 + __ldg(&b_bb[1]))));
        out[b * 4 + 2] = 1.f / (1.f + expf(-(a2 + __ldg(&b_bb[2]))));
        out[b * 4 + 3] = 1.f / (1.f + expf(-(a3 + __ldg(&b_bb[3]))));
    }
}

extern "C" void kernel_launch(void* const* d_in, const int* in_sizes, int n_in,
                              void* d_out, int out_size) {
    const float* x0    = (const float*)d_in[0];
    const float* flow  = (const float*)d_in[1];
    const float* h     = (const float*)d_in[2];
    const float* W_in  = (const float*)d_in[3];
    const float* W_x   = (const float*)d_in[4];
    const float* W_dt  = (const float*)d_in[5];
    const float* b_dt  = (const float*)d_in[6];
    const float* A_log = (const float*)d_in[7];
    const float* Dv    = (const float*)d_in[8];
    const float* W1    = (const float*)d_in[9];
    const float* b1    = (const float*)d_in[10];
    const float* W2    = (const float*)d_in[11];
    const float* b2    = (const float*)d_in[12];
    const float* gamma = (const float*)d_in[13];
    const float* beta  = (const float*)d_in[14];
    const float* W_bb  = (const float*)d_in[15];
    const float* b_bb  = (const float*)d_in[16];

    float* out   = (float*)d_out;                 // (B, 4)
    float* h_new = out + (size_t)BTOT * 4;        // (B, 256, 16)

    const int GSMEM = 2 * 32768 + 128;
    cudaFuncSetAttribute(k_hgemm<256, 512, 0>,
                         cudaFuncAttributeMaxDynamicSharedMemorySize, GSMEM);
    cudaFuncSetAttribute(k_hgemm<256, 512, 1>,
                         cudaFuncAttributeMaxDynamicSharedMemorySize, GSMEM);
    cudaFuncSetAttribute(k_hgemm<512, 256, 2>,
                         cudaFuncAttributeMaxDynamicSharedMemorySize, GSMEM);
    const int XSMEM = (48 * 257 + 64 * 257 + 64 * 17) * 4;
    cudaFuncSetAttribute(k_xdbl,
                         cudaFuncAttributeMaxDynamicSharedMemorySize, XSMEM);

    k_flagset<<<1, 1>>>();
    k_prep<<<16, 256>>>(A_log);
    k_packw<<<512, 256>>>(W_in, 256, 0);
    k_packw<<<512, 256>>>(W1, 256, 1);
    k_packw<<<512, 256>>>(W2, 512, 2);
    k_embed<<<BTOT, 256>>>(x0);
    k_hgemm<256, 512, 0><<<dim3(4, BTOT / 128), 256, GSMEM>>>((const float*)nullptr);
    k_xdbl<<<BTOT / 64, 256, XSMEM>>>(flow, W_x, W_dt, b_dt);
    k_mamba<<<BTOT, 256>>>(h, Dv, h_new);
    k_hgemm<256, 512, 1><<<dim3(4, BTOT / 128), 256, GSMEM>>>(b1);
    k_hgemm<512, 256, 2><<<dim3(2, BTOT / 128), 256, GSMEM>>>(b2);
    k_head<<<BTOT / 8, 256>>>(gamma, beta, W_bb, b_bb, out);
}

// round 10
// speedup vs baseline: 1.0328x; 1.0328x over previous
#include <cuda_runtime.h>
#include <cuda_bf16.h>
#include <math.h>
#include <stdint.h>

#define BTOT 32768
#define NDM 256
#define NDI 256
#define NDS 16
#define NFF 512

// ---- scratch (static device globals; no allocation) ----
__device__ float g_u[(size_t)BTOT*NDI];
__device__ float g_gate[(size_t)BTOT*NDI];
__device__ float g_delta[(size_t)BTOT*NDI];
__device__ float g_Bm[(size_t)BTOT*NDS];
__device__ float g_Cm[(size_t)BTOT*NDS];
__device__ float g_y[(size_t)BTOT*NDI];
__device__ float g_s[(size_t)BTOT*NDM];
__device__ float g_negA[NDI*NDS];

// packed split-bf16 activations: row = [hi(0..K-1) | lo(0..K-1)]
__device__ __nv_bfloat16 g_pospk[(size_t)BTOT*512];   // K=256
__device__ __nv_bfloat16 g_ypk[(size_t)BTOT*512];     // K=256
__device__ __nv_bfloat16 g_tpk[(size_t)BTOT*1024];    // K=512
// packed split-bf16 weights: row n = [hi(0..K-1) | lo(0..K-1)]
__device__ __nv_bfloat16 g_W0pk[512*512];
__device__ __nv_bfloat16 g_W1pk[512*512];
__device__ __nv_bfloat16 g_W2pk[256*1024];

__device__ __forceinline__ float siluf(float x) { return x / (1.f + __expf(-x)); }

__device__ __forceinline__ void packsplit(float v, __nv_bfloat16* hi_p, __nv_bfloat16* lo_p) {
    __nv_bfloat16 hi = __float2bfloat16(v);
    *hi_p = hi;
    *lo_p = __float2bfloat16(v - __bfloat162float(hi));
}

// ---------------- K0a: precompute -exp(A_log) ----------------
__global__ void k_prep(const float* __restrict__ A_log) {
    int i = blockIdx.x * 256 + threadIdx.x;
    g_negA[i] = -expf(A_log[i]);
}

// ---------------- K0b: pack weights to split bf16 ----------------
__global__ void k_packw(const float* __restrict__ W, int K, int sel) {
    int i = blockIdx.x * 256 + threadIdx.x;    // over rows*K
    int n = i / K, k = i - n * K;
    __nv_bfloat16* dst = sel == 0 ? g_W0pk : (sel == 1 ? g_W1pk : g_W2pk);
    float v = W[i];
    __nv_bfloat16 hi = __float2bfloat16(v);
    dst[(size_t)n * 2 * K + k] = hi;
    dst[(size_t)n * 2 * K + K + k] = __float2bfloat16(v - __bfloat162float(hi));
}

// ---------------- K1: sine embedding (writes packed bf16 split) ----------------
__global__ void __launch_bounds__(256) k_embed(const float* __restrict__ x0) {
    int idx = blockIdx.x * 256 + threadIdx.x;        // over BTOT*256
    int b = idx >> 8;
    int c = idx & 255;
    int a = c >> 6;
    int w = c & 63;
    int j = w >> 1;
    float v = x0[b * 4 + a];
    float freq_inv = __expf(-(float)j * 0.28782313662425576f); // ln(10000)/32
    float p = v * 6.283185307179586f * freq_inv;
    float val = (w & 1) ? __cosf(p) : __sinf(p);
    packsplit(val, &g_pospk[(size_t)b * 512 + c], &g_pospk[(size_t)b * 512 + 256 + c]);
}

// ================= HMMA split-bf16 GEMM, merged 3-product chunks, cp.async =================
// C[m,n] = sum_k A[m,k]*W[n,k], D = Ah*Wh + Ah*Wl + Al*Wh in ONE pass per K-chunk.
// MODE 0: A=g_pospk K=256, NOUT=512: n<256 -> g_u=silu(v), else g_gate=v
// MODE 1: A=g_ypk   K=256, NOUT=512: g_tpk = packsplit(relu(v + b1[n]))
// MODE 2: A=g_tpk   K=512, NOUT=256: g_s = v + b2[n] + g_y[m,n]

__device__ __forceinline__ void ldsm_x4(uint32_t* a, uint32_t addr) {
    asm volatile("ldmatrix.sync.aligned.m8n8.x4.shared.b16 {%0,%1,%2,%3}, [%4];"
                 : "=r"(a[0]), "=r"(a[1]), "=r"(a[2]), "=r"(a[3]) : "r"(addr));
}
__device__ __forceinline__ void mma16816(float* d, const uint32_t* a, const uint32_t* b) {
    asm volatile(
        "mma.sync.aligned.m16n8k16.row.col.f32.bf16.bf16.f32 "
        "{%0,%1,%2,%3}, {%4,%5,%6,%7}, {%8,%9}, {%0,%1,%2,%3};"
        : "+f"(d[0]), "+f"(d[1]), "+f"(d[2]), "+f"(d[3])
        : "r"(a[0]), "r"(a[1]), "r"(a[2]), "r"(a[3]), "r"(b[0]), "r"(b[1]));
}
__device__ __forceinline__ void cp16(uint32_t smem, const void* gmem) {
    asm volatile("cp.async.cg.shared.global [%0], [%1], 16;"
                 :: "r"(smem), "l"(gmem));
}
__device__ __forceinline__ void cp_commit() {
    asm volatile("cp.async.commit_group;");
}
template <int N>
__device__ __forceinline__ void cp_wait() {
    asm volatile("cp.async.wait_group %0;" :: "n"(N));
}

template <int KDIM, int NOUT, int MODE>
__global__ void __launch_bounds__(256) k_hgemm(const float* __restrict__ bias) {
    extern __shared__ char smem_raw[];
    const __nv_bfloat16* __restrict__ Apk =
        MODE == 0 ? g_pospk : (MODE == 1 ? g_ypk : g_tpk);
    const __nv_bfloat16* __restrict__ Wpk =
        MODE == 0 ? g_W0pk : (MODE == 1 ? g_W1pk : g_W2pk);

    constexpr int KD2 = 2 * KDIM;
    constexpr int KCH = KDIM / 64;      // merged 64-col chunks
    constexpr int STG = 65536;          // Ah 16K | Al 16K | Wh 16K | Wl 16K

    const int tid = threadIdx.x;
    const int wid = tid >> 5;
    const int lane = tid & 31;
    const int wm = wid & 1;             // 2 m-blocks of 64
    const int wn = wid >> 1;            // 4 n-blocks of 32
    const int m0 = blockIdx.y * 128;
    const int n0 = blockIdx.x * 128;
    uint32_t sb = (uint32_t)__cvta_generic_to_shared(smem_raw);
    sb = (sb + 127u) & ~127u;

    const int sr = tid >> 3;            // 0..31 (x4 steps of 32 rows)
    const int sc = tid & 7;             // 16B group
    const uint32_t soff = (uint32_t)(((sc ^ (sr & 7)) * 16));

    auto stage = [&](int kc, int buf) {
        uint32_t base = sb + buf * STG;
        const __nv_bfloat16* agh = Apk + (size_t)(m0 + sr) * KD2 + kc * 64 + sc * 8;
        const __nv_bfloat16* wgh = Wpk + (size_t)(n0 + sr) * KD2 + kc * 64 + sc * 8;
#pragma unroll
        for (int i = 0; i < 4; i++) {
            uint32_t ro = (uint32_t)((sr + i * 32) * 128) + soff;
            const __nv_bfloat16* ag = agh + (size_t)i * 32 * KD2;
            const __nv_bfloat16* wg = wgh + (size_t)i * 32 * KD2;
            cp16(base + ro, ag);                    // Ah
            cp16(base + 16384 + ro, ag + KDIM);     // Al
            cp16(base + 32768 + ro, wg);            // Wh
            cp16(base + 49152 + ro, wg + KDIM);     // Wl
        }
    };

    float acc[4][4][4];
#pragma unroll
    for (int i = 0; i < 4; i++)
#pragma unroll
        for (int j = 0; j < 4; j++)
#pragma unroll
            for (int q = 0; q < 4; q++) acc[i][j][q] = 0.f;

    stage(0, 0);
    cp_commit();

#pragma unroll 1
    for (int c = 0; c < KCH; c++) {
        if (c + 1 < KCH) {
            stage(c + 1, (c + 1) & 1);
            cp_commit();
            cp_wait<1>();
        } else {
            cp_wait<0>();
        }
        __syncthreads();
        uint32_t bAh = sb + (c & 1) * STG;
        uint32_t bAl = bAh + 16384;
        uint32_t bWh = bAh + 32768;
        uint32_t bWl = bAh + 49152;
#pragma unroll
        for (int ks = 0; ks < 4; ks++) {
            uint32_t ah[4][4], al[4][4], bh[4][2], bl[4][2];
#pragma unroll
            for (int i = 0; i < 4; i++) {
                int r = wm * 64 + i * 16 + (lane & 15);
                int cc = ks * 2 + (lane >> 4);
                uint32_t off = (uint32_t)(r * 128 + ((cc ^ (r & 7)) * 16));
                ldsm_x4(ah[i], bAh + off);
                ldsm_x4(al[i], bAl + off);
            }
#pragma unroll
            for (int jp = 0; jp < 2; jp++) {
                int jj = jp * 2 + (lane >> 4);
                int cc = ks * 2 + ((lane >> 3) & 1);
                int r = wn * 32 + jj * 8 + (lane & 7);
                uint32_t off = (uint32_t)(r * 128 + ((cc ^ (r & 7)) * 16));
                ldsm_x4(&bh[jp * 2][0], bWh + off);
                ldsm_x4(&bl[jp * 2][0], bWl + off);
            }
#pragma unroll
            for (int i = 0; i < 4; i++)
#pragma unroll
                for (int j = 0; j < 4; j++) {
                    mma16816(acc[i][j], ah[i], bh[j]);
                    mma16816(acc[i][j], ah[i], bl[j]);
                    mma16816(acc[i][j], al[i], bh[j]);
                }
        }
        __syncthreads();
    }

    // epilogue: d0=(g,t2), d1=(g,t2+1), d2=(g+8,t2), d3=(g+8,t2+1)
    const int g = lane >> 2;
    const int t2 = (lane & 3) * 2;
#pragma unroll
    for (int i = 0; i < 4; i++) {
#pragma unroll
        for (int j = 0; j < 4; j++) {
#pragma unroll
            for (int h = 0; h < 2; h++) {
                int m = m0 + wm * 64 + i * 16 + g + h * 8;
                int nb = n0 + wn * 32 + j * 8 + t2;
#pragma unroll
                for (int e = 0; e < 2; e++) {
                    int n = nb + e;
                    float v = acc[i][j][h * 2 + e];
                    if (MODE == 0) {
                        if (n < 256) g_u[(size_t)m * 256 + n] = siluf(v);
                        else         g_gate[(size_t)m * 256 + n - 256] = v;
                    } else if (MODE == 1) {
                        float t = fmaxf(v + __ldg(&bias[n]), 0.f);
                        packsplit(t, &g_tpk[(size_t)m * 1024 + n],
                                     &g_tpk[(size_t)m * 1024 + 512 + n]);
                    } else {
                        g_s[(size_t)m * 256 + n] =
                            v + __ldg(&bias[n]) + g_y[(size_t)m * 256 + n];
                    }
                }
            }
        }
    }
}

// ---------------- K3: x_dbl = flow @ W_x^T, col-split across blockIdx.y ----------------
__global__ void __launch_bounds__(256) k_xdbl(const float* __restrict__ flow,
                                              const float* __restrict__ W_x,
                                              const float* __restrict__ W_dt,
                                              const float* __restrict__ b_dt) {
    __shared__ float sW[16][260];
    __shared__ float sF[16][260];
    __shared__ float sdlt[16][17];
    const int b0 = blockIdx.x * 16;
    const int cb = blockIdx.y;
    const int tid = threadIdx.x;

#pragma unroll
    for (int i = 0; i < 4; i++) {
        int f = tid + i * 256;
        int r = f >> 6;
        int c4 = (f & 63) << 2;
        *(float4*)&sW[r][c4] = __ldg((const float4*)(W_x + (size_t)(cb * 16 + r) * 256 + c4));
        *(float4*)&sF[r][c4] = *(const float4*)(flow + (size_t)(b0 + r) * 256 + c4);
    }
    __syncthreads();

    {
        int row = tid >> 4;
        int col = tid & 15;
        float s = 0.f;
#pragma unroll 16
        for (int k = 0; k < 256; k += 4) {
            float4 w = *(const float4*)&sW[col][k];
            float4 f = *(const float4*)&sF[row][k];
            s += w.x * f.x + w.y * f.y + w.z * f.z + w.w * f.w;
        }
        int b = b0 + row;
        if (cb == 0)      sdlt[row][col] = s;
        else if (cb == 1) g_Bm[(size_t)b * 16 + col] = s;
        else              g_Cm[(size_t)b * 16 + col] = s;
    }

    if (cb != 0) return;
    __syncthreads();

    int d = tid;
    float4 wd0 = __ldg((const float4*)(W_dt + d * 16));
    float4 wd1 = __ldg((const float4*)(W_dt + d * 16 + 4));
    float4 wd2 = __ldg((const float4*)(W_dt + d * 16 + 8));
    float4 wd3 = __ldg((const float4*)(W_dt + d * 16 + 12));
    float bd = __ldg(&b_dt[d]);
#pragma unroll 4
    for (int row = 0; row < 16; row++) {
        const float* dl = &sdlt[row][0];
        float s = bd;
        s += wd0.x * dl[0]  + wd0.y * dl[1]  + wd0.z * dl[2]  + wd0.w * dl[3];
        s += wd1.x * dl[4]  + wd1.y * dl[5]  + wd1.z * dl[6]  + wd1.w * dl[7];
        s += wd2.x * dl[8]  + wd2.y * dl[9]  + wd2.z * dl[10] + wd2.w * dl[11];
        s += wd3.x * dl[12] + wd3.y * dl[13] + wd3.z * dl[14] + wd3.w * dl[15];
        g_delta[(size_t)(b0 + row) * 256 + d] = log1pf(expf(s));
    }
}

// ---------------- K4: SSM state update (also writes packed y) ----------------
__global__ void __launch_bounds__(256) k_mamba(const float* __restrict__ h,
                                               const float* __restrict__ Dv,
                                               float* __restrict__ h_new) {
    int b = blockIdx.x;
    int d = threadIdx.x;
    __shared__ float sB[16], sC[16];
    if (d < 16)       sB[d] = g_Bm[(size_t)b * 16 + d];
    else if (d < 32)  sC[d - 16] = g_Cm[(size_t)b * 16 + d - 16];
    __syncthreads();

    size_t base = (size_t)b * 256 + d;
    float delta = g_delta[base];
    float u = g_u[base];
    float du = delta * u;
    const float4* hp = (const float4*)(h + base * 16);
    float4* op = (float4*)(h_new + base * 16);
    const float4* ap = (const float4*)(g_negA + d * 16);
    float y = 0.f;
#pragma unroll
    for (int q = 0; q < 4; q++) {
        float4 hv = __ldcs(&hp[q]);
        float4 al = __ldg(&ap[q]);
        float4 o;
        o.x = __expf(al.x * delta) * hv.x + du * sB[q * 4 + 0];
        o.y = __expf(al.y * delta) * hv.y + du * sB[q * 4 + 1];
        o.z = __expf(al.z * delta) * hv.z + du * sB[q * 4 + 2];
        o.w = __expf(al.w * delta) * hv.w + du * sB[q * 4 + 3];
        __stcs(&op[q], o);
        y += o.x * sC[q * 4 + 0] + o.y * sC[q * 4 + 1]
           + o.z * sC[q * 4 + 2] + o.w * sC[q * 4 + 3];
    }
    y += u * __ldg(&Dv[d]);
    float g = g_gate[base];
    float yv = y * siluf(g);
    g_y[base] = yv;
    packsplit(yv, &g_ypk[(size_t)b * 512 + d], &g_ypk[(size_t)b * 512 + 256 + d]);
}

// ---------------- K7: LayerNorm + 4-way head + sigmoid; warp per row ----------------
__global__ void __launch_bounds__(256) k_head(const float* __restrict__ gamma,
                                              const float* __restrict__ beta,
                                              const float* __restrict__ W_bb,
                                              const float* __restrict__ b_bb,
                                              float* __restrict__ out) {
    int warp = threadIdx.x >> 5;
    int lane = threadIdx.x & 31;
    int b = blockIdx.x * 8 + warp;
    const float* srow = g_s + (size_t)b * 256;

    float v[8];
    float sum = 0.f;
#pragma unroll
    for (int i = 0; i < 8; i++) { v[i] = srow[i * 32 + lane]; sum += v[i]; }
#pragma unroll
    for (int o = 16; o > 0; o >>= 1) sum += __shfl_xor_sync(0xffffffffu, sum, o);
    float mu = sum * (1.f / 256.f);
    float sq = 0.f;
#pragma unroll
    for (int i = 0; i < 8; i++) { float dd = v[i] - mu; sq += dd * dd; }
#pragma unroll
    for (int o = 16; o > 0; o >>= 1) sq += __shfl_xor_sync(0xffffffffu, sq, o);
    float inv = rsqrtf(sq * (1.f / 256.f) + 1e-5f);

    float a0 = 0.f, a1 = 0.f, a2 = 0.f, a3 = 0.f;
#pragma unroll
    for (int i = 0; i < 8; i++) {
        int c = i * 32 + lane;
        float sn = (v[i] - mu) * inv * __ldg(&gamma[c]) + __ldg(&beta[c]);
        a0 += sn * __ldg(&W_bb[c]);
        a1 += sn * __ldg(&W_bb[256 + c]);
        a2 += sn * __ldg(&W_bb[512 + c]);
        a3 += sn * __ldg(&W_bb[768 + c]);
    }
#pragma unroll
    for (int o = 16; o > 0; o >>= 1) {
        a0 += __shfl_xor_sync(0xffffffffu, a0, o);
        a1 += __shfl_xor_sync(0xffffffffu, a1, o);
        a2 += __shfl_xor_sync(0xffffffffu, a2, o);
        a3 += __shfl_xor_sync(0xffffffffu, a3, o);
    }
    if (lane == 0) {
        out[b * 4 + 0] = 1.f / (1.f + expf(-(a0 + __ldg(&b_bb[0]))));
        out[b * 4 + 1] = 1.f / (1.f + expf(-(a1 + __ldg(&b_bb[1]))));
        out[b * 4 + 2] = 1.f / (1.f + expf(-(a2 + __ldg(&b_bb[2]))));
        out[b * 4 + 3] = 1.f / (1.f + expf(-(a3 + __ldg(&b_bb[3]))));
    }
}

extern "C" void kernel_launch(void* const* d_in, const int* in_sizes, int n_in,
                              void* d_out, int out_size) {
    const float* x0    = (const float*)d_in[0];
    const float* flow  = (const float*)d_in[1];
    const float* h     = (const float*)d_in[2];
    const float* W_in  = (const float*)d_in[3];
    const float* W_x   = (const float*)d_in[4];
    const float* W_dt  = (const float*)d_in[5];
    const float* b_dt  = (const float*)d_in[6];
    const float* A_log = (const float*)d_in[7];
    const float* Dv    = (const float*)d_in[8];
    const float* W1    = (const float*)d_in[9];
    const float* b1    = (const float*)d_in[10];
    const float* W2    = (const float*)d_in[11];
    const float* b2    = (const float*)d_in[12];
    const float* gamma = (const float*)d_in[13];
    const float* beta  = (const float*)d_in[14];
    const float* W_bb  = (const float*)d_in[15];
    const float* b_bb  = (const float*)d_in[16];

    float* out   = (float*)d_out;                 // (B, 4)
    float* h_new = out + (size_t)BTOT * 4;        // (B, 256, 16)

    const int GSMEM = 2 * 65536 + 128;
    cudaFuncSetAttribute(k_hgemm<256, 512, 0>,
                         cudaFuncAttributeMaxDynamicSharedMemorySize, GSMEM);
    cudaFuncSetAttribute(k_hgemm<256, 512, 1>,
                         cudaFuncAttributeMaxDynamicSharedMemorySize, GSMEM);
    cudaFuncSetAttribute(k_hgemm<512, 256, 2>,
                         cudaFuncAttributeMaxDynamicSharedMemorySize, GSMEM);

    k_prep<<<16, 256>>>(A_log);
    k_packw<<<512, 256>>>(W_in, 256, 0);
    k_packw<<<512, 256>>>(W1, 256, 1);
    k_packw<<<512, 256>>>(W2, 512, 2);
    k_embed<<<BTOT, 256>>>(x0);
    k_hgemm<256, 512, 0><<<dim3(4, BTOT / 128), 256, GSMEM>>>((const float*)nullptr);
    k_xdbl<<<dim3(BTOT / 16, 3), 256>>>(flow, W_x, W_dt, b_dt);
    k_mamba<<<BTOT, 256>>>(h, Dv, h_new);
    k_hgemm<256, 512, 1><<<dim3(4, BTOT / 128), 256, GSMEM>>>(b1);
    k_hgemm<512, 256, 2><<<dim3(2, BTOT / 128), 256, GSMEM>>>(b2);
    k_head<<<BTOT / 8, 256>>>(gamma, beta, W_bb, b_bb, out);
}

// round 11
// speedup vs baseline: 1.0840x; 1.0496x over previous
#include <cuda_runtime.h>
#include <cuda_bf16.h>
#include <math.h>
#include <stdint.h>

#define BTOT 32768
#define NDM 256
#define NDI 256
#define NDS 16
#define NFF 512

// ---- scratch (static device globals; no allocation) ----
__device__ float g_u[(size_t)BTOT*NDI];
__device__ float g_gate[(size_t)BTOT*NDI];
__device__ float g_delta[(size_t)BTOT*NDI];
__device__ float g_Bm[(size_t)BTOT*NDS];
__device__ float g_Cm[(size_t)BTOT*NDS];
__device__ float g_y[(size_t)BTOT*NDI];
__device__ float g_s[(size_t)BTOT*NDM];
__device__ float g_negA[NDI*NDS];

// packed split-bf16 activations: row = [hi(0..K-1) | lo(0..K-1)]
__device__ __nv_bfloat16 g_pospk[(size_t)BTOT*512];   // K=256
__device__ __nv_bfloat16 g_ypk[(size_t)BTOT*512];     // K=256
__device__ __nv_bfloat16 g_tpk[(size_t)BTOT*1024];    // K=512
// packed split-bf16 weights: row n = [hi(0..K-1) | lo(0..K-1)]
__device__ __nv_bfloat16 g_W0pk[512*512];
__device__ __nv_bfloat16 g_W1pk[512*512];
__device__ __nv_bfloat16 g_W2pk[256*1024];

__device__ __forceinline__ float siluf(float x) { return x / (1.f + __expf(-x)); }

__device__ __forceinline__ void packsplit(float v, __nv_bfloat16* hi_p, __nv_bfloat16* lo_p) {
    __nv_bfloat16 hi = __float2bfloat16(v);
    *hi_p = hi;
    *lo_p = __float2bfloat16(v - __bfloat162float(hi));
}

// ---------------- K0a: precompute -exp(A_log) ----------------
__global__ void k_prep(const float* __restrict__ A_log) {
    int i = blockIdx.x * 256 + threadIdx.x;
    g_negA[i] = -expf(A_log[i]);
}

// ---------------- K0b: pack weights to split bf16 ----------------
__global__ void k_packw(const float* __restrict__ W, int K, int sel) {
    int i = blockIdx.x * 256 + threadIdx.x;    // over rows*K
    int n = i / K, k = i - n * K;
    __nv_bfloat16* dst = sel == 0 ? g_W0pk : (sel == 1 ? g_W1pk : g_W2pk);
    float v = W[i];
    __nv_bfloat16 hi = __float2bfloat16(v);
    dst[(size_t)n * 2 * K + k] = hi;
    dst[(size_t)n * 2 * K + K + k] = __float2bfloat16(v - __bfloat162float(hi));
}

// ---------------- K1: sine embedding (writes packed bf16 split) ----------------
__global__ void __launch_bounds__(256) k_embed(const float* __restrict__ x0) {
    int idx = blockIdx.x * 256 + threadIdx.x;        // over BTOT*256
    int b = idx >> 8;
    int c = idx & 255;
    int a = c >> 6;
    int w = c & 63;
    int j = w >> 1;
    float v = x0[b * 4 + a];
    float freq_inv = __expf(-(float)j * 0.28782313662425576f); // ln(10000)/32
    float p = v * 6.283185307179586f * freq_inv;
    float val = (w & 1) ? __cosf(p) : __sinf(p);
    packsplit(val, &g_pospk[(size_t)b * 512 + c], &g_pospk[(size_t)b * 512 + 256 + c]);
}

// ================= HMMA (mma.sync bf16) split-bf16 GEMM, cp.async pipelined =================
__device__ __forceinline__ void ldsm_x4(uint32_t* a, uint32_t addr) {
    asm volatile("ldmatrix.sync.aligned.m8n8.x4.shared.b16 {%0,%1,%2,%3}, [%4];"
                 : "=r"(a[0]), "=r"(a[1]), "=r"(a[2]), "=r"(a[3]) : "r"(addr));
}
__device__ __forceinline__ void ldsm_x2(uint32_t* b, uint32_t addr) {
    asm volatile("ldmatrix.sync.aligned.m8n8.x2.shared.b16 {%0,%1}, [%2];"
                 : "=r"(b[0]), "=r"(b[1]) : "r"(addr));
}
__device__ __forceinline__ void mma16816(float* d, const uint32_t* a, const uint32_t* b) {
    asm volatile(
        "mma.sync.aligned.m16n8k16.row.col.f32.bf16.bf16.f32 "
        "{%0,%1,%2,%3}, {%4,%5,%6,%7}, {%8,%9}, {%0,%1,%2,%3};"
        : "+f"(d[0]), "+f"(d[1]), "+f"(d[2]), "+f"(d[3])
        : "r"(a[0]), "r"(a[1]), "r"(a[2]), "r"(a[3]), "r"(b[0]), "r"(b[1]));
}
__device__ __forceinline__ void cp16(uint32_t smem, const void* gmem) {
    asm volatile("cp.async.cg.shared.global [%0], [%1], 16;"
                 :: "r"(smem), "l"(gmem));
}
__device__ __forceinline__ void cp_commit() {
    asm volatile("cp.async.commit_group;");
}
template <int N>
__device__ __forceinline__ void cp_wait() {
    asm volatile("cp.async.wait_group %0;" :: "n"(N));
}

template <int KDIM, int NOUT, int MODE>
__global__ void __launch_bounds__(256) k_hgemm(const float* __restrict__ bias) {
    extern __shared__ char smem_raw[];
    const __nv_bfloat16* __restrict__ Apk =
        MODE == 0 ? g_pospk : (MODE == 1 ? g_ypk : g_tpk);
    const __nv_bfloat16* __restrict__ Wpk =
        MODE == 0 ? g_W0pk : (MODE == 1 ? g_W1pk : g_W2pk);

    constexpr int KD2 = 2 * KDIM;
    constexpr int KCH = KDIM / 64;      // 64-col chunks per pass
    constexpr int NCH = 3 * KCH;        // total chunks over 3 passes
    constexpr int STG = 32768;          // stage size: 16KB A + 16KB B

    const int tid = threadIdx.x;
    const int wid = tid >> 5;
    const int lane = tid & 31;
    const int wm = wid & 1;
    const int wn = wid >> 1;
    const int m0 = blockIdx.y * 128;
    const int n0 = blockIdx.x * 128;
    uint32_t sb = (uint32_t)__cvta_generic_to_shared(smem_raw);
    sb = (sb + 127u) & ~127u;

    const int sr = tid >> 3;
    const int sc = tid & 7;
    const uint32_t soff = (uint32_t)(((sc ^ (sr & 7)) * 16));

    auto stage = [&](int c, int buf) {
        int pass = c / KCH;
        int kc = (c - pass * KCH) * 64;
        int acol = (pass == 2 ? KDIM : 0) + kc;
        int bcol = (pass == 1 ? KDIM : 0) + kc;
        uint32_t abase = sb + buf * STG;
        uint32_t bbase = abase + 16384;
        const __nv_bfloat16* ag = Apk + (size_t)(m0 + sr) * KD2 + acol + sc * 8;
        const __nv_bfloat16* wg = Wpk + (size_t)(n0 + sr) * KD2 + bcol + sc * 8;
#pragma unroll
        for (int i = 0; i < 4; i++) {
            int r = sr + i * 32;
            cp16(abase + r * 128 + soff, ag + (size_t)i * 32 * KD2);
            cp16(bbase + r * 128 + soff, wg + (size_t)i * 32 * KD2);
        }
    };

    float acc[4][4][4];
#pragma unroll
    for (int i = 0; i < 4; i++)
#pragma unroll
        for (int j = 0; j < 4; j++)
#pragma unroll
            for (int q = 0; q < 4; q++) acc[i][j][q] = 0.f;

    stage(0, 0);
    cp_commit();

#pragma unroll 1
    for (int c = 0; c < NCH; c++) {
        if (c + 1 < NCH) {
            stage(c + 1, (c + 1) & 1);
            cp_commit();
            cp_wait<1>();
        } else {
            cp_wait<0>();
        }
        __syncthreads();
        uint32_t sAb = sb + (c & 1) * STG;
        uint32_t sBb = sAb + 16384;
#pragma unroll
        for (int ks = 0; ks < 4; ks++) {
            uint32_t afr[4][4], bfr[4][2];
#pragma unroll
            for (int i = 0; i < 4; i++) {
                int r = wm * 64 + i * 16 + (lane & 15);
                int cc = ks * 2 + (lane >> 4);
                ldsm_x4(afr[i], sAb + r * 128 + ((cc ^ (r & 7)) * 16));
            }
#pragma unroll
            for (int j = 0; j < 4; j++) {
                int r = wn * 32 + j * 8 + (lane & 7);
                int cc = ks * 2 + ((lane >> 3) & 1);
                ldsm_x2(bfr[j], sBb + r * 128 + ((cc ^ (r & 7)) * 16));
            }
#pragma unroll
            for (int i = 0; i < 4; i++)
#pragma unroll
                for (int j = 0; j < 4; j++) mma16816(acc[i][j], afr[i], bfr[j]);
        }
        __syncthreads();
    }

    const int g = lane >> 2;
    const int t2 = (lane & 3) * 2;
#pragma unroll
    for (int i = 0; i < 4; i++) {
#pragma unroll
        for (int j = 0; j < 4; j++) {
#pragma unroll
            for (int h = 0; h < 2; h++) {
                int m = m0 + wm * 64 + i * 16 + g + h * 8;
                int nb = n0 + wn * 32 + j * 8 + t2;
#pragma unroll
                for (int e = 0; e < 2; e++) {
                    int n = nb + e;
                    float v = acc[i][j][h * 2 + e];
                    if (MODE == 0) {
                        if (n < 256) g_u[(size_t)m * 256 + n] = siluf(v);
                        else         g_gate[(size_t)m * 256 + n - 256] = v;
                    } else if (MODE == 1) {
                        float t = fmaxf(v + __ldg(&bias[n]), 0.f);
                        packsplit(t, &g_tpk[(size_t)m * 1024 + n],
                                     &g_tpk[(size_t)m * 1024 + 512 + n]);
                    } else {
                        g_s[(size_t)m * 256 + n] =
                            v + __ldg(&bias[n]) + g_y[(size_t)m * 256 + n];
                    }
                }
            }
        }
    }
}

// ---------------- K3: x_dbl = flow @ W_x^T, col-split across blockIdx.y ----------------
__global__ void __launch_bounds__(256) k_xdbl(const float* __restrict__ flow,
                                              const float* __restrict__ W_x,
                                              const float* __restrict__ W_dt,
                                              const float* __restrict__ b_dt) {
    __shared__ float sW[16][260];
    __shared__ float sF[16][260];
    __shared__ float sdlt[16][17];
    const int b0 = blockIdx.x * 16;
    const int cb = blockIdx.y;
    const int tid = threadIdx.x;

#pragma unroll
    for (int i = 0; i < 4; i++) {
        int f = tid + i * 256;
        int r = f >> 6;
        int c4 = (f & 63) << 2;
        *(float4*)&sW[r][c4] = __ldg((const float4*)(W_x + (size_t)(cb * 16 + r) * 256 + c4));
        *(float4*)&sF[r][c4] = *(const float4*)(flow + (size_t)(b0 + r) * 256 + c4);
    }
    __syncthreads();

    {
        int row = tid >> 4;
        int col = tid & 15;
        float s = 0.f;
#pragma unroll 16
        for (int k = 0; k < 256; k += 4) {
            float4 w = *(const float4*)&sW[col][k];
            float4 f = *(const float4*)&sF[row][k];
            s += w.x * f.x + w.y * f.y + w.z * f.z + w.w * f.w;
        }
        int b = b0 + row;
        if (cb == 0)      sdlt[row][col] = s;
        else if (cb == 1) g_Bm[(size_t)b * 16 + col] = s;
        else              g_Cm[(size_t)b * 16 + col] = s;
    }

    if (cb != 0) return;
    __syncthreads();

    int d = tid;
    float4 wd0 = __ldg((const float4*)(W_dt + d * 16));
    float4 wd1 = __ldg((const float4*)(W_dt + d * 16 + 4));
    float4 wd2 = __ldg((const float4*)(W_dt + d * 16 + 8));
    float4 wd3 = __ldg((const float4*)(W_dt + d * 16 + 12));
    float bd = __ldg(&b_dt[d]);
#pragma unroll 4
    for (int row = 0; row < 16; row++) {
        const float* dl = &sdlt[row][0];
        float s = bd;
        s += wd0.x * dl[0]  + wd0.y * dl[1]  + wd0.z * dl[2]  + wd0.w * dl[3];
        s += wd1.x * dl[4]  + wd1.y * dl[5]  + wd1.z * dl[6]  + wd1.w * dl[7];
        s += wd2.x * dl[8]  + wd2.y * dl[9]  + wd2.z * dl[10] + wd2.w * dl[11];
        s += wd3.x * dl[12] + wd3.y * dl[13] + wd3.z * dl[14] + wd3.w * dl[15];
        g_delta[(size_t)(b0 + row) * 256 + d] = log1pf(expf(s));
    }
}

// ---------------- K4: SSM state update (also writes packed y) ----------------
__global__ void __launch_bounds__(256) k_mamba(const float* __restrict__ h,
                                               const float* __restrict__ Dv,
                                               float* __restrict__ h_new) {
    int b = blockIdx.x;
    int d = threadIdx.x;
    __shared__ float sB[16], sC[16];
    if (d < 16)       sB[d] = g_Bm[(size_t)b * 16 + d];
    else if (d < 32)  sC[d - 16] = g_Cm[(size_t)b * 16 + d - 16];
    __syncthreads();

    size_t base = (size_t)b * 256 + d;
    float delta = g_delta[base];
    float u = g_u[base];
    float du = delta * u;
    const float4* hp = (const float4*)(h + base * 16);
    float4* op = (float4*)(h_new + base * 16);
    const float4* ap = (const float4*)(g_negA + d * 16);
    float y = 0.f;
#pragma unroll
    for (int q = 0; q < 4; q++) {
        float4 hv = __ldcs(&hp[q]);
        float4 al = __ldg(&ap[q]);
        float4 o;
        o.x = __expf(al.x * delta) * hv.x + du * sB[q * 4 + 0];
        o.y = __expf(al.y * delta) * hv.y + du * sB[q * 4 + 1];
        o.z = __expf(al.z * delta) * hv.z + du * sB[q * 4 + 2];
        o.w = __expf(al.w * delta) * hv.w + du * sB[q * 4 + 3];
        __stcs(&op[q], o);
        y += o.x * sC[q * 4 + 0] + o.y * sC[q * 4 + 1]
           + o.z * sC[q * 4 + 2] + o.w * sC[q * 4 + 3];
    }
    y += u * __ldg(&Dv[d]);
    float g = g_gate[base];
    float yv = y * siluf(g);
    g_y[base] = yv;
    packsplit(yv, &g_ypk[(size_t)b * 512 + d], &g_ypk[(size_t)b * 512 + 256 + d]);
}

// ---------------- K7: LayerNorm + 4-way head + sigmoid; warp per row ----------------
__global__ void __launch_bounds__(256) k_head(const float* __restrict__ gamma,
                                              const float* __restrict__ beta,
                                              const float* __restrict__ W_bb,
                                              const float* __restrict__ b_bb,
                                              float* __restrict__ out) {
    int warp = threadIdx.x >> 5;
    int lane = threadIdx.x & 31;
    int b = blockIdx.x * 8 + warp;
    const float* srow = g_s + (size_t)b * 256;

    float v[8];
    float sum = 0.f;
#pragma unroll
    for (int i = 0; i < 8; i++) { v[i] = srow[i * 32 + lane]; sum += v[i]; }
#pragma unroll
    for (int o = 16; o > 0; o >>= 1) sum += __shfl_xor_sync(0xffffffffu, sum, o);
    float mu = sum * (1.f / 256.f);
    float sq = 0.f;
#pragma unroll
    for (int i = 0; i < 8; i++) { float dd = v[i] - mu; sq += dd * dd; }
#pragma unroll
    for (int o = 16; o > 0; o >>= 1) sq += __shfl_xor_sync(0xffffffffu, sq, o);
    float inv = rsqrtf(sq * (1.f / 256.f) + 1e-5f);

    float a0 = 0.f, a1 = 0.f, a2 = 0.f, a3 = 0.f;
#pragma unroll
    for (int i = 0; i < 8; i++) {
        int c = i * 32 + lane;
        float sn = (v[i] - mu) * inv * __ldg(&gamma[c]) + __ldg(&beta[c]);
        a0 += sn * __ldg(&W_bb[c]);
        a1 += sn * __ldg(&W_bb[256 + c]);
        a2 += sn * __ldg(&W_bb[512 + c]);
        a3 += sn * __ldg(&W_bb[768 + c]);
    }
#pragma unroll
    for (int o = 16; o > 0; o >>= 1) {
        a0 += __shfl_xor_sync(0xffffffffu, a0, o);
        a1 += __shfl_xor_sync(0xffffffffu, a1, o);
        a2 += __shfl_xor_sync(0xffffffffu, a2, o);
        a3 += __shfl_xor_sync(0xffffffffu, a3, o);
    }
    if (lane == 0) {
        out[b * 4 + 0] = 1.f / (1.f + expf(-(a0 + __ldg(&b_bb[0]))));
        out[b * 4 + 1] = 1.f / (1.f + expf(-(a1 + __ldg(&b_bb[1]))));
        out[b * 4 + 2] = 1.f / (1.f + expf(-(a2 + __ldg(&b_bb[2]))));
        out[b * 4 + 3] = 1.f / (1.f + expf(-(a3 + __ldg(&b_bb[3]))));
    }
}

extern "C" void kernel_launch(void* const* d_in, const int* in_sizes, int n_in,
                              void* d_out, int out_size) {
    const float* x0    = (const float*)d_in[0];
    const float* flow  = (const float*)d_in[1];
    const float* h     = (const float*)d_in[2];
    const float* W_in  = (const float*)d_in[3];
    const float* W_x   = (const float*)d_in[4];
    const float* W_dt  = (const float*)d_in[5];
    const float* b_dt  = (const float*)d_in[6];
    const float* A_log = (const float*)d_in[7];
    const float* Dv    = (const float*)d_in[8];
    const float* W1    = (const float*)d_in[9];
    const float* b1    = (const float*)d_in[10];
    const float* W2    = (const float*)d_in[11];
    const float* b2    = (const float*)d_in[12];
    const float* gamma = (const float*)d_in[13];
    const float* beta  = (const float*)d_in[14];
    const float* W_bb  = (const float*)d_in[15];
    const float* b_bb  = (const float*)d_in[16];

    float* out   = (float*)d_out;                 // (B, 4)
    float* h_new = out + (size_t)BTOT * 4;        // (B, 256, 16)

    const int GSMEM = 2 * 32768 + 128;
    cudaFuncSetAttribute(k_hgemm<256, 512, 0>,
                         cudaFuncAttributeMaxDynamicSharedMemorySize, GSMEM);
    cudaFuncSetAttribute(k_hgemm<256, 512, 1>,
                         cudaFuncAttributeMaxDynamicSharedMemorySize, GSMEM);
    cudaFuncSetAttribute(k_hgemm<512, 256, 2>,
                         cudaFuncAttributeMaxDynamicSharedMemorySize, GSMEM);

    // side stream + events (created once; identical work every call)
    static cudaStream_t s1 = nullptr;
    static cudaEvent_t evFork = nullptr, evJoin = nullptr;
    if (s1 == nullptr) {
        cudaStreamCreateWithFlags(&s1, cudaStreamNonBlocking);
        cudaEventCreateWithFlags(&evFork, cudaEventDisableTiming);
        cudaEventCreateWithFlags(&evJoin, cudaEventDisableTiming);
    }

    // main stream: weight pack for GEMM0 + embed + GEMM0
    k_packw<<<512, 256>>>(W_in, 256, 0);
    cudaEventRecord(evFork, 0);
    cudaStreamWaitEvent(s1, evFork, 0);

    // side stream: everything k_mamba/h_gemm1/2 need that is independent of GEMM0
    k_prep<<<16, 256, 0, s1>>>(A_log);
    k_packw<<<512, 256, 0, s1>>>(W1, 256, 1);
    k_packw<<<512, 256, 0, s1>>>(W2, 512, 2);
    k_xdbl<<<dim3(BTOT / 16, 3), 256, 0, s1>>>(flow, W_x, W_dt, b_dt);
    cudaEventRecord(evJoin, s1);

    k_embed<<<BTOT, 256>>>(x0);
    k_hgemm<256, 512, 0><<<dim3(4, BTOT / 128), 256, GSMEM>>>((const float*)nullptr);

    cudaStreamWaitEvent(0, evJoin, 0);
    k_mamba<<<BTOT, 256>>>(h, Dv, h_new);
    k_hgemm<256, 512, 1><<<dim3(4, BTOT / 128), 256, GSMEM>>>(b1);
    k_hgemm<512, 256, 2><<<dim3(2, BTOT / 128), 256, GSMEM>>>(b2);
    k_head<<<BTOT / 8, 256>>>(gamma, beta, W_bb, b_bb, out);
}

// round 12
// speedup vs baseline: 1.1160x; 1.0295x over previous
#include <cuda_runtime.h>
#include <cuda_bf16.h>
#include <math.h>
#include <stdint.h>

#define BTOT 32768
#define NDM 256
#define NDI 256
#define NDS 16
#define NFF 512

// ---- scratch (static device globals; no allocation) ----
__device__ float g_u[(size_t)BTOT*NDI];
__device__ float g_gate[(size_t)BTOT*NDI];
__device__ float g_delta[(size_t)BTOT*NDI];
__device__ float g_Bm[(size_t)BTOT*NDS];
__device__ float g_Cm[(size_t)BTOT*NDS];
__device__ float g_y[(size_t)BTOT*NDI];
__device__ float g_s[(size_t)BTOT*NDM];
__device__ float g_negA[NDI*NDS];

// packed split-bf16 activations: row = [hi(0..K-1) | lo(0..K-1)]
__device__ __nv_bfloat16 g_pospk[(size_t)BTOT*512];   // K=256
__device__ __nv_bfloat16 g_ypk[(size_t)BTOT*512];     // K=256
__device__ __nv_bfloat16 g_tpk[(size_t)BTOT*1024];    // K=512
// packed split-bf16 weights: row n = [hi(0..K-1) | lo(0..K-1)]
__device__ __nv_bfloat16 g_W0pk[512*512];
__device__ __nv_bfloat16 g_W1pk[512*512];
__device__ __nv_bfloat16 g_W2pk[256*1024];

__device__ __forceinline__ float siluf(float x) { return x / (1.f + __expf(-x)); }

__device__ __forceinline__ void packsplit(float v, __nv_bfloat16* hi_p, __nv_bfloat16* lo_p) {
    __nv_bfloat16 hi = __float2bfloat16(v);
    *hi_p = hi;
    *lo_p = __float2bfloat16(v - __bfloat162float(hi));
}

// ---------------- K0a: precompute -exp(A_log) ----------------
__global__ void k_prep(const float* __restrict__ A_log) {
    int i = blockIdx.x * 256 + threadIdx.x;
    g_negA[i] = -expf(A_log[i]);
}

// ---------------- K0b: pack weights to split bf16 ----------------
__global__ void k_packw(const float* __restrict__ W, int K, int sel) {
    int i = blockIdx.x * 256 + threadIdx.x;    // over rows*K
    int n = i / K, k = i - n * K;
    __nv_bfloat16* dst = sel == 0 ? g_W0pk : (sel == 1 ? g_W1pk : g_W2pk);
    float v = W[i];
    __nv_bfloat16 hi = __float2bfloat16(v);
    dst[(size_t)n * 2 * K + k] = hi;
    dst[(size_t)n * 2 * K + K + k] = __float2bfloat16(v - __bfloat162float(hi));
}

// ---------------- K1: sine embedding (writes packed bf16 split) ----------------
__global__ void __launch_bounds__(256) k_embed(const float* __restrict__ x0) {
    int idx = blockIdx.x * 256 + threadIdx.x;        // over BTOT*256
    int b = idx >> 8;
    int c = idx & 255;
    int a = c >> 6;
    int w = c & 63;
    int j = w >> 1;
    float v = x0[b * 4 + a];
    float freq_inv = __expf(-(float)j * 0.28782313662425576f); // ln(10000)/32
    float p = v * 6.283185307179586f * freq_inv;
    float val = (w & 1) ? __cosf(p) : __sinf(p);
    packsplit(val, &g_pospk[(size_t)b * 512 + c], &g_pospk[(size_t)b * 512 + 256 + c]);
}

// ================= HMMA (mma.sync bf16) split-bf16 GEMM =================
// persistent CTAs + cp.async double buffering + cross-tile prefetch
__device__ __forceinline__ void ldsm_x4(uint32_t* a, uint32_t addr) {
    asm volatile("ldmatrix.sync.aligned.m8n8.x4.shared.b16 {%0,%1,%2,%3}, [%4];"
                 : "=r"(a[0]), "=r"(a[1]), "=r"(a[2]), "=r"(a[3]) : "r"(addr));
}
__device__ __forceinline__ void ldsm_x2(uint32_t* b, uint32_t addr) {
    asm volatile("ldmatrix.sync.aligned.m8n8.x2.shared.b16 {%0,%1}, [%2];"
                 : "=r"(b[0]), "=r"(b[1]) : "r"(addr));
}
__device__ __forceinline__ void mma16816(float* d, const uint32_t* a, const uint32_t* b) {
    asm volatile(
        "mma.sync.aligned.m16n8k16.row.col.f32.bf16.bf16.f32 "
        "{%0,%1,%2,%3}, {%4,%5,%6,%7}, {%8,%9}, {%0,%1,%2,%3};"
        : "+f"(d[0]), "+f"(d[1]), "+f"(d[2]), "+f"(d[3])
        : "r"(a[0]), "r"(a[1]), "r"(a[2]), "r"(a[3]), "r"(b[0]), "r"(b[1]));
}
__device__ __forceinline__ void cp16(uint32_t smem, const void* gmem) {
    asm volatile("cp.async.cg.shared.global [%0], [%1], 16;"
                 :: "r"(smem), "l"(gmem));
}
__device__ __forceinline__ void cp_commit() {
    asm volatile("cp.async.commit_group;");
}
template <int N>
__device__ __forceinline__ void cp_wait() {
    asm volatile("cp.async.wait_group %0;" :: "n"(N));
}

// MODE 0: A=g_pospk K=256, NOUT=512: n<256 -> g_u=silu(v), else g_gate=v
// MODE 1: A=g_ypk   K=256, NOUT=512: g_tpk = packsplit(relu(v + b1[n]))
// MODE 2: A=g_tpk   K=512, NOUT=256: g_s = v + b2[n] + g_y[m,n]
template <int KDIM, int NOUT, int MODE>
__global__ void __launch_bounds__(256) k_hgemm(const float* __restrict__ bias) {
    extern __shared__ char smem_raw[];
    const __nv_bfloat16* __restrict__ Apk =
        MODE == 0 ? g_pospk : (MODE == 1 ? g_ypk : g_tpk);
    const __nv_bfloat16* __restrict__ Wpk =
        MODE == 0 ? g_W0pk : (MODE == 1 ? g_W1pk : g_W2pk);

    constexpr int KD2 = 2 * KDIM;
    constexpr int KCH = KDIM / 64;      // 64-col chunks per pass
    constexpr int NCH = 3 * KCH;        // total chunks over 3 passes (even)
    constexpr int STG = 32768;          // stage size: 16KB A + 16KB B
    constexpr int NX = NOUT / 128;      // tiles along N
    constexpr int NT = (BTOT / 128) * NX;

    const int tid = threadIdx.x;
    const int wid = tid >> 5;
    const int lane = tid & 31;
    const int wm = wid & 1;
    const int wn = wid >> 1;
    uint32_t sb = (uint32_t)__cvta_generic_to_shared(smem_raw);
    sb = (sb + 127u) & ~127u;

    const int sr = tid >> 3;
    const int sc = tid & 7;
    const uint32_t soff = (uint32_t)(((sc ^ (sr & 7)) * 16));

    auto stage = [&](int tile, int c, int buf) {
        int m0 = (tile / NX) * 128;
        int n0 = (tile - (tile / NX) * NX) * 128;
        int pass = c / KCH;
        int kc = (c - pass * KCH) * 64;
        int acol = (pass == 2 ? KDIM : 0) + kc;
        int bcol = (pass == 1 ? KDIM : 0) + kc;
        uint32_t abase = sb + buf * STG;
        uint32_t bbase = abase + 16384;
        const __nv_bfloat16* ag = Apk + (size_t)(m0 + sr) * KD2 + acol + sc * 8;
        const __nv_bfloat16* wg = Wpk + (size_t)(n0 + sr) * KD2 + bcol + sc * 8;
#pragma unroll
        for (int i = 0; i < 4; i++) {
            int r = sr + i * 32;
            cp16(abase + r * 128 + soff, ag + (size_t)i * 32 * KD2);
            cp16(bbase + r * 128 + soff, wg + (size_t)i * 32 * KD2);
        }
    };

    int tile = blockIdx.x;
    if (tile >= NT) return;
    stage(tile, 0, 0);
    cp_commit();

#pragma unroll 1
    for (; tile < NT; tile += gridDim.x) {
        const int m0 = (tile / NX) * 128;
        const int n0 = (tile - (tile / NX) * NX) * 128;
        const int ntile = tile + gridDim.x;

        float acc[4][4][4];
#pragma unroll
        for (int i = 0; i < 4; i++)
#pragma unroll
            for (int j = 0; j < 4; j++)
#pragma unroll
                for (int q = 0; q < 4; q++) acc[i][j][q] = 0.f;

#pragma unroll 1
        for (int c = 0; c < NCH; c++) {
            bool more = (c + 1 < NCH) || (ntile < NT);
            if (c + 1 < NCH)      stage(tile, c + 1, (c + 1) & 1);
            else if (ntile < NT)  stage(ntile, 0, 0);   // NCH even -> buf 0
            if (more) { cp_commit(); cp_wait<1>(); }
            else      { cp_wait<0>(); }
            __syncthreads();
            uint32_t sAb = sb + (c & 1) * STG;
            uint32_t sBb = sAb + 16384;
#pragma unroll
            for (int ks = 0; ks < 4; ks++) {
                uint32_t afr[4][4], bfr[4][2];
#pragma unroll
                for (int i = 0; i < 4; i++) {
                    int r = wm * 64 + i * 16 + (lane & 15);
                    int cc = ks * 2 + (lane >> 4);
                    ldsm_x4(afr[i], sAb + r * 128 + ((cc ^ (r & 7)) * 16));
                }
#pragma unroll
                for (int j = 0; j < 4; j++) {
                    int r = wn * 32 + j * 8 + (lane & 7);
                    int cc = ks * 2 + ((lane >> 3) & 1);
                    ldsm_x2(bfr[j], sBb + r * 128 + ((cc ^ (r & 7)) * 16));
                }
#pragma unroll
                for (int i = 0; i < 4; i++)
#pragma unroll
                    for (int j = 0; j < 4; j++) mma16816(acc[i][j], afr[i], bfr[j]);
            }
            __syncthreads();
        }

        // epilogue (registers + global only; overlaps in-flight prefetch)
        const int g = lane >> 2;
        const int t2 = (lane & 3) * 2;
#pragma unroll
        for (int i = 0; i < 4; i++) {
#pragma unroll
            for (int j = 0; j < 4; j++) {
#pragma unroll
                for (int h = 0; h < 2; h++) {
                    int m = m0 + wm * 64 + i * 16 + g + h * 8;
                    int nb = n0 + wn * 32 + j * 8 + t2;
#pragma unroll
                    for (int e = 0; e < 2; e++) {
                        int n = nb + e;
                        float v = acc[i][j][h * 2 + e];
                        if (MODE == 0) {
                            if (n < 256) g_u[(size_t)m * 256 + n] = siluf(v);
                            else         g_gate[(size_t)m * 256 + n - 256] = v;
                        } else if (MODE == 1) {
                            float t = fmaxf(v + __ldg(&bias[n]), 0.f);
                            packsplit(t, &g_tpk[(size_t)m * 1024 + n],
                                         &g_tpk[(size_t)m * 1024 + 512 + n]);
                        } else {
                            g_s[(size_t)m * 256 + n] =
                                v + __ldg(&bias[n]) + g_y[(size_t)m * 256 + n];
                        }
                    }
                }
            }
        }
    }
}

// ---------------- K3: x_dbl = flow @ W_x^T, col-split across blockIdx.y ----------------
__global__ void __launch_bounds__(256) k_xdbl(const float* __restrict__ flow,
                                              const float* __restrict__ W_x,
                                              const float* __restrict__ W_dt,
                                              const float* __restrict__ b_dt) {
    __shared__ float sW[16][260];
    __shared__ float sF[16][260];
    __shared__ float sdlt[16][17];
    const int b0 = blockIdx.x * 16;
    const int cb = blockIdx.y;
    const int tid = threadIdx.x;

#pragma unroll
    for (int i = 0; i < 4; i++) {
        int f = tid + i * 256;
        int r = f >> 6;
        int c4 = (f & 63) << 2;
        *(float4*)&sW[r][c4] = __ldg((const float4*)(W_x + (size_t)(cb * 16 + r) * 256 + c4));
        *(float4*)&sF[r][c4] = *(const float4*)(flow + (size_t)(b0 + r) * 256 + c4);
    }
    __syncthreads();

    {
        int row = tid >> 4;
        int col = tid & 15;
        float s = 0.f;
#pragma unroll 16
        for (int k = 0; k < 256; k += 4) {
            float4 w = *(const float4*)&sW[col][k];
            float4 f = *(const float4*)&sF[row][k];
            s += w.x * f.x + w.y * f.y + w.z * f.z + w.w * f.w;
        }
        int b = b0 + row;
        if (cb == 0)      sdlt[row][col] = s;
        else if (cb == 1) g_Bm[(size_t)b * 16 + col] = s;
        else              g_Cm[(size_t)b * 16 + col] = s;
    }

    if (cb != 0) return;
    __syncthreads();

    int d = tid;
    float4 wd0 = __ldg((const float4*)(W_dt + d * 16));
    float4 wd1 = __ldg((const float4*)(W_dt + d * 16 + 4));
    float4 wd2 = __ldg((const float4*)(W_dt + d * 16 + 8));
    float4 wd3 = __ldg((const float4*)(W_dt + d * 16 + 12));
    float bd = __ldg(&b_dt[d]);
#pragma unroll 4
    for (int row = 0; row < 16; row++) {
        const float* dl = &sdlt[row][0];
        float s = bd;
        s += wd0.x * dl[0]  + wd0.y * dl[1]  + wd0.z * dl[2]  + wd0.w * dl[3];
        s += wd1.x * dl[4]  + wd1.y * dl[5]  + wd1.z * dl[6]  + wd1.w * dl[7];
        s += wd2.x * dl[8]  + wd2.y * dl[9]  + wd2.z * dl[10] + wd2.w * dl[11];
        s += wd3.x * dl[12] + wd3.y * dl[13] + wd3.z * dl[14] + wd3.w * dl[15];
        g_delta[(size_t)(b0 + row) * 256 + d] = log1pf(expf(s));
    }
}

// ---------------- K4: SSM state update (also writes packed y) ----------------
__global__ void __launch_bounds__(256) k_mamba(const float* __restrict__ h,
                                               const float* __restrict__ Dv,
                                               float* __restrict__ h_new) {
    int b = blockIdx.x;
    int d = threadIdx.x;
    __shared__ float sB[16], sC[16];
    if (d < 16)       sB[d] = g_Bm[(size_t)b * 16 + d];
    else if (d < 32)  sC[d - 16] = g_Cm[(size_t)b * 16 + d - 16];
    __syncthreads();

    size_t base = (size_t)b * 256 + d;
    float delta = g_delta[base];
    float u = g_u[base];
    float du = delta * u;
    const float4* hp = (const float4*)(h + base * 16);
    float4* op = (float4*)(h_new + base * 16);
    const float4* ap = (const float4*)(g_negA + d * 16);
    float y = 0.f;
#pragma unroll
    for (int q = 0; q < 4; q++) {
        float4 hv = __ldcs(&hp[q]);
        float4 al = __ldg(&ap[q]);
        float4 o;
        o.x = __expf(al.x * delta) * hv.x + du * sB[q * 4 + 0];
        o.y = __expf(al.y * delta) * hv.y + du * sB[q * 4 + 1];
        o.z = __expf(al.z * delta) * hv.z + du * sB[q * 4 + 2];
        o.w = __expf(al.w * delta) * hv.w + du * sB[q * 4 + 3];
        __stcs(&op[q], o);
        y += o.x * sC[q * 4 + 0] + o.y * sC[q * 4 + 1]
           + o.z * sC[q * 4 + 2] + o.w * sC[q * 4 + 3];
    }
    y += u * __ldg(&Dv[d]);
    float g = g_gate[base];
    float yv = y * siluf(g);
    g_y[base] = yv;
    packsplit(yv, &g_ypk[(size_t)b * 512 + d], &g_ypk[(size_t)b * 512 + 256 + d]);
}

// ---------------- K7: LayerNorm + 4-way head + sigmoid; warp per row ----------------
__global__ void __launch_bounds__(256) k_head(const float* __restrict__ gamma,
                                              const float* __restrict__ beta,
                                              const float* __restrict__ W_bb,
                                              const float* __restrict__ b_bb,
                                              float* __restrict__ out) {
    int warp = threadIdx.x >> 5;
    int lane = threadIdx.x & 31;
    int b = blockIdx.x * 8 + warp;
    const float* srow = g_s + (size_t)b * 256;

    float v[8];
    float sum = 0.f;
#pragma unroll
    for (int i = 0; i < 8; i++) { v[i] = srow[i * 32 + lane]; sum += v[i]; }
#pragma unroll
    for (int o = 16; o > 0; o >>= 1) sum += __shfl_xor_sync(0xffffffffu, sum, o);
    float mu = sum * (1.f / 256.f);
    float sq = 0.f;
#pragma unroll
    for (int i = 0; i < 8; i++) { float dd = v[i] - mu; sq += dd * dd; }
#pragma unroll
    for (int o = 16; o > 0; o >>= 1) sq += __shfl_xor_sync(0xffffffffu, sq, o);
    float inv = rsqrtf(sq * (1.f / 256.f) + 1e-5f);

    float a0 = 0.f, a1 = 0.f, a2 = 0.f, a3 = 0.f;
#pragma unroll
    for (int i = 0; i < 8; i++) {
        int c = i * 32 + lane;
        float sn = (v[i] - mu) * inv * __ldg(&gamma[c]) + __ldg(&beta[c]);
        a0 += sn * __ldg(&W_bb[c]);
        a1 += sn * __ldg(&W_bb[256 + c]);
        a2 += sn * __ldg(&W_bb[512 + c]);
        a3 += sn * __ldg(&W_bb[768 + c]);
    }
#pragma unroll
    for (int o = 16; o > 0; o >>= 1) {
        a0 += __shfl_xor_sync(0xffffffffu, a0, o);
        a1 += __shfl_xor_sync(0xffffffffu, a1, o);
        a2 += __shfl_xor_sync(0xffffffffu, a2, o);
        a3 += __shfl_xor_sync(0xffffffffu, a3, o);
    }
    if (lane == 0) {
        out[b * 4 + 0] = 1.f / (1.f + expf(-(a0 + __ldg(&b_bb[0]))));
        out[b * 4 + 1] = 1.f / (1.f + expf(-(a1 + __ldg(&b_bb[1]))));
        out[b * 4 + 2] = 1.f / (1.f + expf(-(a2 + __ldg(&b_bb[2]))));
        out[b * 4 + 3] = 1.f / (1.f + expf(-(a3 + __ldg(&b_bb[3]))));
    }
}

extern "C" void kernel_launch(void* const* d_in, const int* in_sizes, int n_in,
                              void* d_out, int out_size) {
    const float* x0    = (const float*)d_in[0];
    const float* flow  = (const float*)d_in[1];
    const float* h     = (const float*)d_in[2];
    const float* W_in  = (const float*)d_in[3];
    const float* W_x   = (const float*)d_in[4];
    const float* W_dt  = (const float*)d_in[5];
    const float* b_dt  = (const float*)d_in[6];
    const float* A_log = (const float*)d_in[7];
    const float* Dv    = (const float*)d_in[8];
    const float* W1    = (const float*)d_in[9];
    const float* b1    = (const float*)d_in[10];
    const float* W2    = (const float*)d_in[11];
    const float* b2    = (const float*)d_in[12];
    const float* gamma = (const float*)d_in[13];
    const float* beta  = (const float*)d_in[14];
    const float* W_bb  = (const float*)d_in[15];
    const float* b_bb  = (const float*)d_in[16];

    float* out   = (float*)d_out;                 // (B, 4)
    float* h_new = out + (size_t)BTOT * 4;        // (B, 256, 16)

    const int GSMEM = 2 * 32768 + 128;
    cudaFuncSetAttribute(k_hgemm<256, 512, 0>,
                         cudaFuncAttributeMaxDynamicSharedMemorySize, GSMEM);
    cudaFuncSetAttribute(k_hgemm<256, 512, 1>,
                         cudaFuncAttributeMaxDynamicSharedMemorySize, GSMEM);
    cudaFuncSetAttribute(k_hgemm<512, 256, 2>,
                         cudaFuncAttributeMaxDynamicSharedMemorySize, GSMEM);
    const int PGRID = 296;   // 148 SMs x 2 CTAs

    // side stream + events (created once; identical work every call)
    static cudaStream_t s1 = nullptr;
    static cudaEvent_t evFork = nullptr, evJoin = nullptr;
    if (s1 == nullptr) {
        cudaStreamCreateWithFlags(&s1, cudaStreamNonBlocking);
        cudaEventCreateWithFlags(&evFork, cudaEventDisableTiming);
        cudaEventCreateWithFlags(&evJoin, cudaEventDisableTiming);
    }

    // main stream: weight pack for GEMM0 + embed + GEMM0
    k_packw<<<512, 256>>>(W_in, 256, 0);
    cudaEventRecord(evFork, 0);
    cudaStreamWaitEvent(s1, evFork, 0);

    // side stream: everything k_mamba/h_gemm1/2 need that is independent of GEMM0
    k_prep<<<16, 256, 0, s1>>>(A_log);
    k_packw<<<512, 256, 0, s1>>>(W1, 256, 1);
    k_packw<<<512, 256, 0, s1>>>(W2, 512, 2);
    k_xdbl<<<dim3(BTOT / 16, 3), 256, 0, s1>>>(flow, W_x, W_dt, b_dt);
    cudaEventRecord(evJoin, s1);

    k_embed<<<BTOT, 256>>>(x0);
    k_hgemm<256, 512, 0><<<PGRID, 256, GSMEM>>>((const float*)nullptr);

    cudaStreamWaitEvent(0, evJoin, 0);
    k_mamba<<<BTOT, 256>>>(h, Dv, h_new);
    k_hgemm<256, 512, 1><<<PGRID, 256, GSMEM>>>(b1);
    k_hgemm<512, 256, 2><<<PGRID, 256, GSMEM>>>(b2);
    k_head<<<BTOT / 8, 256>>>(gamma, beta, W_bb, b_bb, out);
}

// round 13
// speedup vs baseline: 1.1218x; 1.0052x over previous
#include <cuda_runtime.h>
#include <cuda_bf16.h>
#include <math.h>
#include <stdint.h>

#define BTOT 32768
#define NDM 256
#define NDI 256
#define NDS 16
#define NFF 512

// ---- scratch (static device globals; no allocation) ----
__device__ float g_u[(size_t)BTOT*NDI];
__device__ float g_gate[(size_t)BTOT*NDI];
__device__ float g_delta[(size_t)BTOT*NDI];
__device__ float g_Bm[(size_t)BTOT*NDS];
__device__ float g_Cm[(size_t)BTOT*NDS];
__device__ float g_y[(size_t)BTOT*NDI];
__device__ float g_s[(size_t)BTOT*NDM];
__device__ float g_negA[NDI*NDS];

// packed split-bf16 activations: row = [hi(0..K-1) | lo(0..K-1)]
__device__ __nv_bfloat16 g_pospk[(size_t)BTOT*512];   // K=256
__device__ __nv_bfloat16 g_ypk[(size_t)BTOT*512];     // K=256
__device__ __nv_bfloat16 g_tpk[(size_t)BTOT*1024];    // K=512
// packed split-bf16 weights: row n = [hi(0..K-1) | lo(0..K-1)]
__device__ __nv_bfloat16 g_W0pk[512*512];
__device__ __nv_bfloat16 g_W1pk[512*512];
__device__ __nv_bfloat16 g_W2pk[256*1024];

__device__ __forceinline__ float siluf(float x) { return x / (1.f + __expf(-x)); }

__device__ __forceinline__ void packsplit(float v, __nv_bfloat16* hi_p, __nv_bfloat16* lo_p) {
    __nv_bfloat16 hi = __float2bfloat16(v);
    *hi_p = hi;
    *lo_p = __float2bfloat16(v - __bfloat162float(hi));
}

// ---------------- K0a: precompute -exp(A_log) ----------------
__global__ void k_prep(const float* __restrict__ A_log) {
    int i = blockIdx.x * 256 + threadIdx.x;
    g_negA[i] = -expf(A_log[i]);
}

// ---------------- K0b: pack weights to split bf16 ----------------
__global__ void k_packw(const float* __restrict__ W, int K, int sel) {
    int i = blockIdx.x * 256 + threadIdx.x;    // over rows*K
    int n = i / K, k = i - n * K;
    __nv_bfloat16* dst = sel == 0 ? g_W0pk : (sel == 1 ? g_W1pk : g_W2pk);
    float v = W[i];
    __nv_bfloat16 hi = __float2bfloat16(v);
    dst[(size_t)n * 2 * K + k] = hi;
    dst[(size_t)n * 2 * K + K + k] = __float2bfloat16(v - __bfloat162float(hi));
}

// ---------------- K1: sine embedding (writes packed bf16 split) ----------------
__global__ void __launch_bounds__(256) k_embed(const float* __restrict__ x0) {
    int idx = blockIdx.x * 256 + threadIdx.x;        // over BTOT*256
    int b = idx >> 8;
    int c = idx & 255;
    int a = c >> 6;
    int w = c & 63;
    int j = w >> 1;
    float v = x0[b * 4 + a];
    float freq_inv = __expf(-(float)j * 0.28782313662425576f); // ln(10000)/32
    float p = v * 6.283185307179586f * freq_inv;
    float val = (w & 1) ? __cosf(p) : __sinf(p);
    packsplit(val, &g_pospk[(size_t)b * 512 + c], &g_pospk[(size_t)b * 512 + 256 + c]);
}

// ================= HMMA (mma.sync bf16) split-bf16 GEMM =================
// persistent CTAs + cp.async double buffering + cross-tile prefetch
__device__ __forceinline__ void ldsm_x4(uint32_t* a, uint32_t addr) {
    asm volatile("ldmatrix.sync.aligned.m8n8.x4.shared.b16 {%0,%1,%2,%3}, [%4];"
                 : "=r"(a[0]), "=r"(a[1]), "=r"(a[2]), "=r"(a[3]) : "r"(addr));
}
__device__ __forceinline__ void ldsm_x2(uint32_t* b, uint32_t addr) {
    asm volatile("ldmatrix.sync.aligned.m8n8.x2.shared.b16 {%0,%1}, [%2];"
                 : "=r"(b[0]), "=r"(b[1]) : "r"(addr));
}
__device__ __forceinline__ void mma16816(float* d, const uint32_t* a, const uint32_t* b) {
    asm volatile(
        "mma.sync.aligned.m16n8k16.row.col.f32.bf16.bf16.f32 "
        "{%0,%1,%2,%3}, {%4,%5,%6,%7}, {%8,%9}, {%0,%1,%2,%3};"
        : "+f"(d[0]), "+f"(d[1]), "+f"(d[2]), "+f"(d[3])
        : "r"(a[0]), "r"(a[1]), "r"(a[2]), "r"(a[3]), "r"(b[0]), "r"(b[1]));
}
__device__ __forceinline__ void cp16(uint32_t smem, const void* gmem) {
    asm volatile("cp.async.cg.shared.global [%0], [%1], 16;"
                 :: "r"(smem), "l"(gmem));
}
__device__ __forceinline__ void cp_commit() {
    asm volatile("cp.async.commit_group;");
}
template <int N>
__device__ __forceinline__ void cp_wait() {
    asm volatile("cp.async.wait_group %0;" :: "n"(N));
}

// MODE 0: A=g_pospk K=256, NOUT=512: n<256 -> g_u=silu(v), else g_gate=v
// MODE 1: A=g_ypk   K=256, NOUT=512: g_tpk = packsplit(relu(v + b1[n]))
// MODE 2: A=g_tpk   K=512, NOUT=256: g_s = v + b2[n] + g_y[m,n]
template <int KDIM, int NOUT, int MODE>
__global__ void __launch_bounds__(256) k_hgemm(const float* __restrict__ bias) {
    extern __shared__ char smem_raw[];
    const __nv_bfloat16* __restrict__ Apk =
        MODE == 0 ? g_pospk : (MODE == 1 ? g_ypk : g_tpk);
    const __nv_bfloat16* __restrict__ Wpk =
        MODE == 0 ? g_W0pk : (MODE == 1 ? g_W1pk : g_W2pk);

    constexpr int KD2 = 2 * KDIM;
    constexpr int KCH = KDIM / 64;      // 64-col chunks per pass
    constexpr int NCH = 3 * KCH;        // total chunks over 3 passes (even)
    constexpr int STG = 32768;          // stage size: 16KB A + 16KB B
    constexpr int NX = NOUT / 128;      // tiles along N
    constexpr int NT = (BTOT / 128) * NX;

    const int tid = threadIdx.x;
    const int wid = tid >> 5;
    const int lane = tid & 31;
    const int wm = wid & 1;
    const int wn = wid >> 1;
    uint32_t sb = (uint32_t)__cvta_generic_to_shared(smem_raw);
    sb = (sb + 127u) & ~127u;

    const int sr = tid >> 3;
    const int sc = tid & 7;
    const uint32_t soff = (uint32_t)(((sc ^ (sr & 7)) * 16));

    auto stage = [&](int tile, int c, int buf) {
        int m0 = (tile / NX) * 128;
        int n0 = (tile - (tile / NX) * NX) * 128;
        int pass = c / KCH;
        int kc = (c - pass * KCH) * 64;
        int acol = (pass == 2 ? KDIM : 0) + kc;
        int bcol = (pass == 1 ? KDIM : 0) + kc;
        uint32_t abase = sb + buf * STG;
        uint32_t bbase = abase + 16384;
        const __nv_bfloat16* ag = Apk + (size_t)(m0 + sr) * KD2 + acol + sc * 8;
        const __nv_bfloat16* wg = Wpk + (size_t)(n0 + sr) * KD2 + bcol + sc * 8;
#pragma unroll
        for (int i = 0; i < 4; i++) {
            int r = sr + i * 32;
            cp16(abase + r * 128 + soff, ag + (size_t)i * 32 * KD2);
            cp16(bbase + r * 128 + soff, wg + (size_t)i * 32 * KD2);
        }
    };

    int tile = blockIdx.x;
    if (tile >= NT) return;
    stage(tile, 0, 0);
    cp_commit();

#pragma unroll 1
    for (; tile < NT; tile += gridDim.x) {
        const int m0 = (tile / NX) * 128;
        const int n0 = (tile - (tile / NX) * NX) * 128;
        const int ntile = tile + gridDim.x;

        float acc[4][4][4];
#pragma unroll
        for (int i = 0; i < 4; i++)
#pragma unroll
            for (int j = 0; j < 4; j++)
#pragma unroll
                for (int q = 0; q < 4; q++) acc[i][j][q] = 0.f;

#pragma unroll 1
        for (int c = 0; c < NCH; c++) {
            bool more = (c + 1 < NCH) || (ntile < NT);
            if (c + 1 < NCH)      stage(tile, c + 1, (c + 1) & 1);
            else if (ntile < NT)  stage(ntile, 0, 0);   // NCH even -> buf 0
            if (more) { cp_commit(); cp_wait<1>(); }
            else      { cp_wait<0>(); }
            __syncthreads();
            uint32_t sAb = sb + (c & 1) * STG;
            uint32_t sBb = sAb + 16384;
#pragma unroll
            for (int ks = 0; ks < 4; ks++) {
                uint32_t afr[4][4], bfr[4][2];
#pragma unroll
                for (int i = 0; i < 4; i++) {
                    int r = wm * 64 + i * 16 + (lane & 15);
                    int cc = ks * 2 + (lane >> 4);
                    ldsm_x4(afr[i], sAb + r * 128 + ((cc ^ (r & 7)) * 16));
                }
#pragma unroll
                for (int j = 0; j < 4; j++) {
                    int r = wn * 32 + j * 8 + (lane & 7);
                    int cc = ks * 2 + ((lane >> 3) & 1);
                    ldsm_x2(bfr[j], sBb + r * 128 + ((cc ^ (r & 7)) * 16));
                }
#pragma unroll
                for (int i = 0; i < 4; i++)
#pragma unroll
                    for (int j = 0; j < 4; j++) mma16816(acc[i][j], afr[i], bfr[j]);
            }
            __syncthreads();
        }

        // epilogue (registers + global only; overlaps in-flight prefetch)
        const int g = lane >> 2;
        const int t2 = (lane & 3) * 2;
#pragma unroll
        for (int i = 0; i < 4; i++) {
#pragma unroll
            for (int j = 0; j < 4; j++) {
#pragma unroll
                for (int h = 0; h < 2; h++) {
                    int m = m0 + wm * 64 + i * 16 + g + h * 8;
                    int nb = n0 + wn * 32 + j * 8 + t2;
#pragma unroll
                    for (int e = 0; e < 2; e++) {
                        int n = nb + e;
                        float v = acc[i][j][h * 2 + e];
                        if (MODE == 0) {
                            if (n < 256) g_u[(size_t)m * 256 + n] = siluf(v);
                            else         g_gate[(size_t)m * 256 + n - 256] = v;
                        } else if (MODE == 1) {
                            float t = fmaxf(v + __ldg(&bias[n]), 0.f);
                            packsplit(t, &g_tpk[(size_t)m * 1024 + n],
                                         &g_tpk[(size_t)m * 1024 + 512 + n]);
                        } else {
                            g_s[(size_t)m * 256 + n] =
                                v + __ldg(&bias[n]) + g_y[(size_t)m * 256 + n];
                        }
                    }
                }
            }
        }
    }
}

// ---------------- K3: x_dbl = flow @ W_x^T, col-split across blockIdx.y ----------------
__global__ void __launch_bounds__(256) k_xdbl(const float* __restrict__ flow,
                                              const float* __restrict__ W_x,
                                              const float* __restrict__ W_dt,
                                              const float* __restrict__ b_dt) {
    __shared__ float sW[16][260];
    __shared__ float sF[16][260];
    __shared__ float sdlt[16][17];
    const int b0 = blockIdx.x * 16;
    const int cb = blockIdx.y;
    const int tid = threadIdx.x;

#pragma unroll
    for (int i = 0; i < 4; i++) {
        int f = tid + i * 256;
        int r = f >> 6;
        int c4 = (f & 63) << 2;
        *(float4*)&sW[r][c4] = __ldg((const float4*)(W_x + (size_t)(cb * 16 + r) * 256 + c4));
        *(float4*)&sF[r][c4] = *(const float4*)(flow + (size_t)(b0 + r) * 256 + c4);
    }
    __syncthreads();

    {
        int row = tid >> 4;
        int col = tid & 15;
        float s = 0.f;
#pragma unroll 16
        for (int k = 0; k < 256; k += 4) {
            float4 w = *(const float4*)&sW[col][k];
            float4 f = *(const float4*)&sF[row][k];
            s += w.x * f.x + w.y * f.y + w.z * f.z + w.w * f.w;
        }
        int b = b0 + row;
        if (cb == 0)      sdlt[row][col] = s;
        else if (cb == 1) g_Bm[(size_t)b * 16 + col] = s;
        else              g_Cm[(size_t)b * 16 + col] = s;
    }

    if (cb != 0) return;
    __syncthreads();

    int d = tid;
    float4 wd0 = __ldg((const float4*)(W_dt + d * 16));
    float4 wd1 = __ldg((const float4*)(W_dt + d * 16 + 4));
    float4 wd2 = __ldg((const float4*)(W_dt + d * 16 + 8));
    float4 wd3 = __ldg((const float4*)(W_dt + d * 16 + 12));
    float bd = __ldg(&b_dt[d]);
#pragma unroll 4
    for (int row = 0; row < 16; row++) {
        const float* dl = &sdlt[row][0];
        float s = bd;
        s += wd0.x * dl[0]  + wd0.y * dl[1]  + wd0.z * dl[2]  + wd0.w * dl[3];
        s += wd1.x * dl[4]  + wd1.y * dl[5]  + wd1.z * dl[6]  + wd1.w * dl[7];
        s += wd2.x * dl[8]  + wd2.y * dl[9]  + wd2.z * dl[10] + wd2.w * dl[11];
        s += wd3.x * dl[12] + wd3.y * dl[13] + wd3.z * dl[14] + wd3.w * dl[15];
        g_delta[(size_t)(b0 + row) * 256 + d] = log1pf(expf(s));
    }
}

// ---------------- K4: SSM state update, smem-staged coalesced h I/O ----------------
// One block per b. h row (4096 floats) loaded coalesced into padded smem, each
// thread then owns row d (16 floats) with conflict-free stride-5 float4 layout.
__global__ void __launch_bounds__(256) k_mamba(const float* __restrict__ h,
                                               const float* __restrict__ Dv,
                                               float* __restrict__ h_new) {
    __shared__ float4 sh[256 * 5];     // row d at sh[d*5 + q], q=0..3 (1 float4 pad)
    __shared__ float sB[16], sC[16];
    const int b = blockIdx.x;
    const int t = threadIdx.x;
    if (t < 16)       sB[t] = g_Bm[(size_t)b * 16 + t];
    else if (t < 32)  sC[t - 16] = g_Cm[(size_t)b * 16 + t - 16];

    const float4* hp = (const float4*)(h + (size_t)b * 4096);
#pragma unroll
    for (int j = 0; j < 4; j++) {
        int i = t + 256 * j;                       // consecutive lanes -> consecutive float4s
        sh[(i >> 2) * 5 + (i & 3)] = __ldcs(&hp[i]);
    }
    __syncthreads();

    const int d = t;
    const size_t base = (size_t)b * 256 + d;
    const float delta = g_delta[base];
    const float u = g_u[base];
    const float du = delta * u;
    const float4* ap = (const float4*)(g_negA + d * 16);
    float y = 0.f;
#pragma unroll
    for (int q = 0; q < 4; q++) {
        float4 hv = sh[d * 5 + q];
        float4 al = __ldg(&ap[q]);
        float4 o;
        o.x = __expf(al.x * delta) * hv.x + du * sB[q * 4 + 0];
        o.y = __expf(al.y * delta) * hv.y + du * sB[q * 4 + 1];
        o.z = __expf(al.z * delta) * hv.z + du * sB[q * 4 + 2];
        o.w = __expf(al.w * delta) * hv.w + du * sB[q * 4 + 3];
        sh[d * 5 + q] = o;
        y += o.x * sC[q * 4 + 0] + o.y * sC[q * 4 + 1]
           + o.z * sC[q * 4 + 2] + o.w * sC[q * 4 + 3];
    }
    y += u * __ldg(&Dv[d]);
    float g = g_gate[base];
    float yv = y * siluf(g);
    g_y[base] = yv;
    packsplit(yv, &g_ypk[(size_t)b * 512 + d], &g_ypk[(size_t)b * 512 + 256 + d]);
    __syncthreads();

    float4* op = (float4*)(h_new + (size_t)b * 4096);
#pragma unroll
    for (int j = 0; j < 4; j++) {
        int i = t + 256 * j;
        __stcs(&op[i], sh[(i >> 2) * 5 + (i & 3)]);
    }
}

// ---------------- K7: LayerNorm + 4-way head + sigmoid; warp per row ----------------
__global__ void __launch_bounds__(256) k_head(const float* __restrict__ gamma,
                                              const float* __restrict__ beta,
                                              const float* __restrict__ W_bb,
                                              const float* __restrict__ b_bb,
                                              float* __restrict__ out) {
    int warp = threadIdx.x >> 5;
    int lane = threadIdx.x & 31;
    int b = blockIdx.x * 8 + warp;
    const float* srow = g_s + (size_t)b * 256;

    float v[8];
    float sum = 0.f;
#pragma unroll
    for (int i = 0; i < 8; i++) { v[i] = srow[i * 32 + lane]; sum += v[i]; }
#pragma unroll
    for (int o = 16; o > 0; o >>= 1) sum += __shfl_xor_sync(0xffffffffu, sum, o);
    float mu = sum * (1.f / 256.f);
    float sq = 0.f;
#pragma unroll
    for (int i = 0; i < 8; i++) { float dd = v[i] - mu; sq += dd * dd; }
#pragma unroll
    for (int o = 16; o > 0; o >>= 1) sq += __shfl_xor_sync(0xffffffffu, sq, o);
    float inv = rsqrtf(sq * (1.f / 256.f) + 1e-5f);

    float a0 = 0.f, a1 = 0.f, a2 = 0.f, a3 = 0.f;
#pragma unroll
    for (int i = 0; i < 8; i++) {
        int c = i * 32 + lane;
        float sn = (v[i] - mu) * inv * __ldg(&gamma[c]) + __ldg(&beta[c]);
        a0 += sn * __ldg(&W_bb[c]);
        a1 += sn * __ldg(&W_bb[256 + c]);
        a2 += sn * __ldg(&W_bb[512 + c]);
        a3 += sn * __ldg(&W_bb[768 + c]);
    }
#pragma unroll
    for (int o = 16; o > 0; o >>= 1) {
        a0 += __shfl_xor_sync(0xffffffffu, a0, o);
        a1 += __shfl_xor_sync(0xffffffffu, a1, o);
        a2 += __shfl_xor_sync(0xffffffffu, a2, o);
        a3 += __shfl_xor_sync(0xffffffffu, a3, o);
    }
    if (lane == 0) {
        out[b * 4 + 0] = 1.f / (1.f + expf(-(a0 + __ldg(&b_bb[0]))));
        out[b * 4 + 1] = 1.f / (1.f + expf(-(a1 + __ldg(&b_bb[1]))));
        out[b * 4 + 2] = 1.f / (1.f + expf(-(a2 + __ldg(&b_bb[2]))));
        out[b * 4 + 3] = 1.f / (1.f + expf(-(a3 + __ldg(&b_bb[3]))));
    }
}

extern "C" void kernel_launch(void* const* d_in, const int* in_sizes, int n_in,
                              void* d_out, int out_size) {
    const float* x0    = (const float*)d_in[0];
    const float* flow  = (const float*)d_in[1];
    const float* h     = (const float*)d_in[2];
    const float* W_in  = (const float*)d_in[3];
    const float* W_x   = (const float*)d_in[4];
    const float* W_dt  = (const float*)d_in[5];
    const float* b_dt  = (const float*)d_in[6];
    const float* A_log = (const float*)d_in[7];
    const float* Dv    = (const float*)d_in[8];
    const float* W1    = (const float*)d_in[9];
    const float* b1    = (const float*)d_in[10];
    const float* W2    = (const float*)d_in[11];
    const float* b2    = (const float*)d_in[12];
    const float* gamma = (const float*)d_in[13];
    const float* beta  = (const float*)d_in[14];
    const float* W_bb  = (const float*)d_in[15];
    const float* b_bb  = (const float*)d_in[16];

    float* out   = (float*)d_out;                 // (B, 4)
    float* h_new = out + (size_t)BTOT * 4;        // (B, 256, 16)

    const int GSMEM = 2 * 32768 + 128;
    cudaFuncSetAttribute(k_hgemm<256, 512, 0>,
                         cudaFuncAttributeMaxDynamicSharedMemorySize, GSMEM);
    cudaFuncSetAttribute(k_hgemm<256, 512, 1>,
                         cudaFuncAttributeMaxDynamicSharedMemorySize, GSMEM);
    cudaFuncSetAttribute(k_hgemm<512, 256, 2>,
                         cudaFuncAttributeMaxDynamicSharedMemorySize, GSMEM);
    const int PGRID = 296;   // 148 SMs x 2 CTAs

    // side stream + events (created once; identical work every call)
    static cudaStream_t s1 = nullptr;
    static cudaEvent_t evFork = nullptr, evJoin = nullptr;
    if (s1 == nullptr) {
        cudaStreamCreateWithFlags(&s1, cudaStreamNonBlocking);
        cudaEventCreateWithFlags(&evFork, cudaEventDisableTiming);
        cudaEventCreateWithFlags(&evJoin, cudaEventDisableTiming);
    }

    // main stream: weight pack for GEMM0 + embed + GEMM0
    k_packw<<<512, 256>>>(W_in, 256, 0);
    cudaEventRecord(evFork, 0);
    cudaStreamWaitEvent(s1, evFork, 0);

    // side stream: everything k_mamba/h_gemm1/2 need that is independent of GEMM0
    k_prep<<<16, 256, 0, s1>>>(A_log);
    k_packw<<<512, 256, 0, s1>>>(W1, 256, 1);
    k_packw<<<512, 256, 0, s1>>>(W2, 512, 2);
    k_xdbl<<<dim3(BTOT / 16, 3), 256, 0, s1>>>(flow, W_x, W_dt, b_dt);
    cudaEventRecord(evJoin, s1);

    k_embed<<<BTOT, 256>>>(x0);
    k_hgemm<256, 512, 0><<<PGRID, 256, GSMEM>>>((const float*)nullptr);

    cudaStreamWaitEvent(0, evJoin, 0);
    k_mamba<<<BTOT, 256>>>(h, Dv, h_new);
    k_hgemm<256, 512, 1><<<PGRID, 256, GSMEM>>>(b1);
    k_hgemm<512, 256, 2><<<PGRID, 256, GSMEM>>>(b2);
    k_head<<<BTOT / 8, 256>>>(gamma, beta, W_bb, b_bb, out);
}

// round 14
// speedup vs baseline: 1.1463x; 1.0218x over previous
#include <cuda_runtime.h>
#include <cuda_bf16.h>
#include <math.h>
#include <stdint.h>

#define BTOT 32768
#define BHALF 16384
#define NDM 256
#define NDI 256
#define NDS 16
#define NFF 512

// ---- scratch (static device globals; no allocation) ----
__device__ float g_u[(size_t)BTOT*NDI];
__device__ float g_gate[(size_t)BTOT*NDI];
__device__ float g_delta[(size_t)BTOT*NDI];
__device__ float g_Bm[(size_t)BTOT*NDS];
__device__ float g_Cm[(size_t)BTOT*NDS];
__device__ float g_y[(size_t)BTOT*NDI];
__device__ float g_s[(size_t)BTOT*NDM];
__device__ float g_negA[NDI*NDS];

// packed split-bf16 activations: row = [hi(0..K-1) | lo(0..K-1)]
__device__ __nv_bfloat16 g_pospk[(size_t)BTOT*512];   // K=256
__device__ __nv_bfloat16 g_ypk[(size_t)BTOT*512];     // K=256
__device__ __nv_bfloat16 g_tpk[(size_t)BTOT*1024];    // K=512
// packed split-bf16 weights: row n = [hi(0..K-1) | lo(0..K-1)]
__device__ __nv_bfloat16 g_W0pk[512*512];
__device__ __nv_bfloat16 g_W1pk[512*512];
__device__ __nv_bfloat16 g_W2pk[256*1024];

__device__ __forceinline__ float siluf(float x) { return x / (1.f + __expf(-x)); }

__device__ __forceinline__ void packsplit(float v, __nv_bfloat16* hi_p, __nv_bfloat16* lo_p) {
    __nv_bfloat16 hi = __float2bfloat16(v);
    *hi_p = hi;
    *lo_p = __float2bfloat16(v - __bfloat162float(hi));
}

// ---------------- K0a: precompute -exp(A_log) ----------------
__global__ void k_prep(const float* __restrict__ A_log) {
    int i = blockIdx.x * 256 + threadIdx.x;
    g_negA[i] = -expf(A_log[i]);
}

// ---------------- K0b: pack weights to split bf16 ----------------
__global__ void k_packw(const float* __restrict__ W, int K, int sel) {
    int i = blockIdx.x * 256 + threadIdx.x;    // over rows*K
    int n = i / K, k = i - n * K;
    __nv_bfloat16* dst = sel == 0 ? g_W0pk : (sel == 1 ? g_W1pk : g_W2pk);
    float v = W[i];
    __nv_bfloat16 hi = __float2bfloat16(v);
    dst[(size_t)n * 2 * K + k] = hi;
    dst[(size_t)n * 2 * K + K + k] = __float2bfloat16(v - __bfloat162float(hi));
}

// ---------------- K1: sine embedding (writes packed bf16 split) ----------------
__global__ void __launch_bounds__(256) k_embed(const float* __restrict__ x0, int boff) {
    int b = boff + blockIdx.x;
    int c = threadIdx.x;
    int a = c >> 6;
    int w = c & 63;
    int j = w >> 1;
    float v = x0[b * 4 + a];
    float freq_inv = __expf(-(float)j * 0.28782313662425576f); // ln(10000)/32
    float p = v * 6.283185307179586f * freq_inv;
    float val = (w & 1) ? __cosf(p) : __sinf(p);
    packsplit(val, &g_pospk[(size_t)b * 512 + c], &g_pospk[(size_t)b * 512 + 256 + c]);
}

// ================= HMMA (mma.sync bf16) split-bf16 GEMM =================
// persistent CTAs + cp.async double buffering + cross-tile prefetch
__device__ __forceinline__ void ldsm_x4(uint32_t* a, uint32_t addr) {
    asm volatile("ldmatrix.sync.aligned.m8n8.x4.shared.b16 {%0,%1,%2,%3}, [%4];"
                 : "=r"(a[0]), "=r"(a[1]), "=r"(a[2]), "=r"(a[3]) : "r"(addr));
}
__device__ __forceinline__ void ldsm_x2(uint32_t* b, uint32_t addr) {
    asm volatile("ldmatrix.sync.aligned.m8n8.x2.shared.b16 {%0,%1}, [%2];"
                 : "=r"(b[0]), "=r"(b[1]) : "r"(addr));
}
__device__ __forceinline__ void mma16816(float* d, const uint32_t* a, const uint32_t* b) {
    asm volatile(
        "mma.sync.aligned.m16n8k16.row.col.f32.bf16.bf16.f32 "
        "{%0,%1,%2,%3}, {%4,%5,%6,%7}, {%8,%9}, {%0,%1,%2,%3};"
        : "+f"(d[0]), "+f"(d[1]), "+f"(d[2]), "+f"(d[3])
        : "r"(a[0]), "r"(a[1]), "r"(a[2]), "r"(a[3]), "r"(b[0]), "r"(b[1]));
}
__device__ __forceinline__ void cp16(uint32_t smem, const void* gmem) {
    asm volatile("cp.async.cg.shared.global [%0], [%1], 16;"
                 :: "r"(smem), "l"(gmem));
}
__device__ __forceinline__ void cp_commit() {
    asm volatile("cp.async.commit_group;");
}
template <int N>
__device__ __forceinline__ void cp_wait() {
    asm volatile("cp.async.wait_group %0;" :: "n"(N));
}

// MODE 0: A=g_pospk K=256, NOUT=512: n<256 -> g_u=silu(v), else g_gate=v
// MODE 1: A=g_ypk   K=256, NOUT=512: g_tpk = packsplit(relu(v + b1[n]))
// MODE 2: A=g_tpk   K=512, NOUT=256: g_s = v + b2[n] + g_y[m,n]
template <int KDIM, int NOUT, int MODE>
__global__ void __launch_bounds__(256) k_hgemm(const float* __restrict__ bias, int mbase) {
    extern __shared__ char smem_raw[];
    const __nv_bfloat16* __restrict__ Apk =
        MODE == 0 ? g_pospk : (MODE == 1 ? g_ypk : g_tpk);
    const __nv_bfloat16* __restrict__ Wpk =
        MODE == 0 ? g_W0pk : (MODE == 1 ? g_W1pk : g_W2pk);

    constexpr int KD2 = 2 * KDIM;
    constexpr int KCH = KDIM / 64;      // 64-col chunks per pass
    constexpr int NCH = 3 * KCH;        // total chunks over 3 passes (even)
    constexpr int STG = 32768;          // stage size: 16KB A + 16KB B
    constexpr int NX = NOUT / 128;      // tiles along N
    constexpr int NT = (BHALF / 128) * NX;

    const int tid = threadIdx.x;
    const int wid = tid >> 5;
    const int lane = tid & 31;
    const int wm = wid & 1;
    const int wn = wid >> 1;
    uint32_t sb = (uint32_t)__cvta_generic_to_shared(smem_raw);
    sb = (sb + 127u) & ~127u;

    const int sr = tid >> 3;
    const int sc = tid & 7;
    const uint32_t soff = (uint32_t)(((sc ^ (sr & 7)) * 16));

    auto stage = [&](int tile, int c, int buf) {
        int m0 = mbase + (tile / NX) * 128;
        int n0 = (tile - (tile / NX) * NX) * 128;
        int pass = c / KCH;
        int kc = (c - pass * KCH) * 64;
        int acol = (pass == 2 ? KDIM : 0) + kc;
        int bcol = (pass == 1 ? KDIM : 0) + kc;
        uint32_t abase = sb + buf * STG;
        uint32_t bbase = abase + 16384;
        const __nv_bfloat16* ag = Apk + (size_t)(m0 + sr) * KD2 + acol + sc * 8;
        const __nv_bfloat16* wg = Wpk + (size_t)(n0 + sr) * KD2 + bcol + sc * 8;
#pragma unroll
        for (int i = 0; i < 4; i++) {
            int r = sr + i * 32;
            cp16(abase + r * 128 + soff, ag + (size_t)i * 32 * KD2);
            cp16(bbase + r * 128 + soff, wg + (size_t)i * 32 * KD2);
        }
    };

    int tile = blockIdx.x;
    if (tile >= NT) return;
    stage(tile, 0, 0);
    cp_commit();

#pragma unroll 1
    for (; tile < NT; tile += gridDim.x) {
        const int m0 = mbase + (tile / NX) * 128;
        const int n0 = (tile - (tile / NX) * NX) * 128;
        const int ntile = tile + gridDim.x;

        float acc[4][4][4];
#pragma unroll
        for (int i = 0; i < 4; i++)
#pragma unroll
            for (int j = 0; j < 4; j++)
#pragma unroll
                for (int q = 0; q < 4; q++) acc[i][j][q] = 0.f;

#pragma unroll 1
        for (int c = 0; c < NCH; c++) {
            bool more = (c + 1 < NCH) || (ntile < NT);
            if (c + 1 < NCH)      stage(tile, c + 1, (c + 1) & 1);
            else if (ntile < NT)  stage(ntile, 0, 0);   // NCH even -> buf 0
            if (more) { cp_commit(); cp_wait<1>(); }
            else      { cp_wait<0>(); }
            __syncthreads();
            uint32_t sAb = sb + (c & 1) * STG;
            uint32_t sBb = sAb + 16384;
#pragma unroll
            for (int ks = 0; ks < 4; ks++) {
                uint32_t afr[4][4], bfr[4][2];
#pragma unroll
                for (int i = 0; i < 4; i++) {
                    int r = wm * 64 + i * 16 + (lane & 15);
                    int cc = ks * 2 + (lane >> 4);
                    ldsm_x4(afr[i], sAb + r * 128 + ((cc ^ (r & 7)) * 16));
                }
#pragma unroll
                for (int j = 0; j < 4; j++) {
                    int r = wn * 32 + j * 8 + (lane & 7);
                    int cc = ks * 2 + ((lane >> 3) & 1);
                    ldsm_x2(bfr[j], sBb + r * 128 + ((cc ^ (r & 7)) * 16));
                }
#pragma unroll
                for (int i = 0; i < 4; i++)
#pragma unroll
                    for (int j = 0; j < 4; j++) mma16816(acc[i][j], afr[i], bfr[j]);
            }
            __syncthreads();
        }

        // epilogue (registers + global only; overlaps in-flight prefetch)
        const int g = lane >> 2;
        const int t2 = (lane & 3) * 2;
#pragma unroll
        for (int i = 0; i < 4; i++) {
#pragma unroll
            for (int j = 0; j < 4; j++) {
#pragma unroll
                for (int h = 0; h < 2; h++) {
                    int m = m0 + wm * 64 + i * 16 + g + h * 8;
                    int nb = n0 + wn * 32 + j * 8 + t2;
#pragma unroll
                    for (int e = 0; e < 2; e++) {
                        int n = nb + e;
                        float v = acc[i][j][h * 2 + e];
                        if (MODE == 0) {
                            if (n < 256) g_u[(size_t)m * 256 + n] = siluf(v);
                            else         g_gate[(size_t)m * 256 + n - 256] = v;
                        } else if (MODE == 1) {
                            float t = fmaxf(v + __ldg(&bias[n]), 0.f);
                            packsplit(t, &g_tpk[(size_t)m * 1024 + n],
                                         &g_tpk[(size_t)m * 1024 + 512 + n]);
                        } else {
                            g_s[(size_t)m * 256 + n] =
                                v + __ldg(&bias[n]) + g_y[(size_t)m * 256 + n];
                        }
                    }
                }
            }
        }
    }
}

// ---------------- K3: x_dbl = flow @ W_x^T, col-split across blockIdx.y ----------------
__global__ void __launch_bounds__(256) k_xdbl(const float* __restrict__ flow,
                                              const float* __restrict__ W_x,
                                              const float* __restrict__ W_dt,
                                              const float* __restrict__ b_dt, int boff) {
    __shared__ float sW[16][260];
    __shared__ float sF[16][260];
    __shared__ float sdlt[16][17];
    const int b0 = boff + blockIdx.x * 16;
    const int cb = blockIdx.y;
    const int tid = threadIdx.x;

#pragma unroll
    for (int i = 0; i < 4; i++) {
        int f = tid + i * 256;
        int r = f >> 6;
        int c4 = (f & 63) << 2;
        *(float4*)&sW[r][c4] = __ldg((const float4*)(W_x + (size_t)(cb * 16 + r) * 256 + c4));
        *(float4*)&sF[r][c4] = *(const float4*)(flow + (size_t)(b0 + r) * 256 + c4);
    }
    __syncthreads();

    {
        int row = tid >> 4;
        int col = tid & 15;
        float s = 0.f;
#pragma unroll 16
        for (int k = 0; k < 256; k += 4) {
            float4 w = *(const float4*)&sW[col][k];
            float4 f = *(const float4*)&sF[row][k];
            s += w.x * f.x + w.y * f.y + w.z * f.z + w.w * f.w;
        }
        int b = b0 + row;
        if (cb == 0)      sdlt[row][col] = s;
        else if (cb == 1) g_Bm[(size_t)b * 16 + col] = s;
        else              g_Cm[(size_t)b * 16 + col] = s;
    }

    if (cb != 0) return;
    __syncthreads();

    int d = tid;
    float4 wd0 = __ldg((const float4*)(W_dt + d * 16));
    float4 wd1 = __ldg((const float4*)(W_dt + d * 16 + 4));
    float4 wd2 = __ldg((const float4*)(W_dt + d * 16 + 8));
    float4 wd3 = __ldg((const float4*)(W_dt + d * 16 + 12));
    float bd = __ldg(&b_dt[d]);
#pragma unroll 4
    for (int row = 0; row < 16; row++) {
        const float* dl = &sdlt[row][0];
        float s = bd;
        s += wd0.x * dl[0]  + wd0.y * dl[1]  + wd0.z * dl[2]  + wd0.w * dl[3];
        s += wd1.x * dl[4]  + wd1.y * dl[5]  + wd1.z * dl[6]  + wd1.w * dl[7];
        s += wd2.x * dl[8]  + wd2.y * dl[9]  + wd2.z * dl[10] + wd2.w * dl[11];
        s += wd3.x * dl[12] + wd3.y * dl[13] + wd3.z * dl[14] + wd3.w * dl[15];
        g_delta[(size_t)(b0 + row) * 256 + d] = log1pf(expf(s));
    }
}

// ---------------- K4: SSM state update, smem-staged coalesced h I/O ----------------
__global__ void __launch_bounds__(256) k_mamba(const float* __restrict__ h,
                                               const float* __restrict__ Dv,
                                               float* __restrict__ h_new, int boff) {
    __shared__ float4 sh[256 * 5];     // row d at sh[d*5 + q], q=0..3 (1 float4 pad)
    __shared__ float sB[16], sC[16];
    const int b = boff + blockIdx.x;
    const int t = threadIdx.x;
    if (t < 16)       sB[t] = g_Bm[(size_t)b * 16 + t];
    else if (t < 32)  sC[t - 16] = g_Cm[(size_t)b * 16 + t - 16];

    const float4* hp = (const float4*)(h + (size_t)b * 4096);
#pragma unroll
    for (int j = 0; j < 4; j++) {
        int i = t + 256 * j;
        sh[(i >> 2) * 5 + (i & 3)] = __ldcs(&hp[i]);
    }
    __syncthreads();

    const int d = t;
    const size_t base = (size_t)b * 256 + d;
    const float delta = g_delta[base];
    const float u = g_u[base];
    const float du = delta * u;
    const float4* ap = (const float4*)(g_negA + d * 16);
    float y = 0.f;
#pragma unroll
    for (int q = 0; q < 4; q++) {
        float4 hv = sh[d * 5 + q];
        float4 al = __ldg(&ap[q]);
        float4 o;
        o.x = __expf(al.x * delta) * hv.x + du * sB[q * 4 + 0];
        o.y = __expf(al.y * delta) * hv.y + du * sB[q * 4 + 1];
        o.z = __expf(al.z * delta) * hv.z + du * sB[q * 4 + 2];
        o.w = __expf(al.w * delta) * hv.w + du * sB[q * 4 + 3];
        sh[d * 5 + q] = o;
        y += o.x * sC[q * 4 + 0] + o.y * sC[q * 4 + 1]
           + o.z * sC[q * 4 + 2] + o.w * sC[q * 4 + 3];
    }
    y += u * __ldg(&Dv[d]);
    float g = g_gate[base];
    float yv = y * siluf(g);
    g_y[base] = yv;
    packsplit(yv, &g_ypk[(size_t)b * 512 + d], &g_ypk[(size_t)b * 512 + 256 + d]);
    __syncthreads();

    float4* op = (float4*)(h_new + (size_t)b * 4096);
#pragma unroll
    for (int j = 0; j < 4; j++) {
        int i = t + 256 * j;
        __stcs(&op[i], sh[(i >> 2) * 5 + (i & 3)]);
    }
}

// ---------------- K7: LayerNorm + 4-way head + sigmoid; warp per row ----------------
__global__ void __launch_bounds__(256) k_head(const float* __restrict__ gamma,
                                              const float* __restrict__ beta,
                                              const float* __restrict__ W_bb,
                                              const float* __restrict__ b_bb,
                                              float* __restrict__ out, int boff) {
    int warp = threadIdx.x >> 5;
    int lane = threadIdx.x & 31;
    int b = boff + blockIdx.x * 8 + warp;
    const float* srow = g_s + (size_t)b * 256;

    float v[8];
    float sum = 0.f;
#pragma unroll
    for (int i = 0; i < 8; i++) { v[i] = srow[i * 32 + lane]; sum += v[i]; }
#pragma unroll
    for (int o = 16; o > 0; o >>= 1) sum += __shfl_xor_sync(0xffffffffu, sum, o);
    float mu = sum * (1.f / 256.f);
    float sq = 0.f;
#pragma unroll
    for (int i = 0; i < 8; i++) { float dd = v[i] - mu; sq += dd * dd; }
#pragma unroll
    for (int o = 16; o > 0; o >>= 1) sq += __shfl_xor_sync(0xffffffffu, sq, o);
    float inv = rsqrtf(sq * (1.f / 256.f) + 1e-5f);

    float a0 = 0.f, a1 = 0.f, a2 = 0.f, a3 = 0.f;
#pragma unroll
    for (int i = 0; i < 8; i++) {
        int c = i * 32 + lane;
        float sn = (v[i] - mu) * inv * __ldg(&gamma[c]) + __ldg(&beta[c]);
        a0 += sn * __ldg(&W_bb[c]);
        a1 += sn * __ldg(&W_bb[256 + c]);
        a2 += sn * __ldg(&W_bb[512 + c]);
        a3 += sn * __ldg(&W_bb[768 + c]);
    }
#pragma unroll
    for (int o = 16; o > 0; o >>= 1) {
        a0 += __shfl_xor_sync(0xffffffffu, a0, o);
        a1 += __shfl_xor_sync(0xffffffffu, a1, o);
        a2 += __shfl_xor_sync(0xffffffffu, a2, o);
        a3 += __shfl_xor_sync(0xffffffffu, a3, o);
    }
    if (lane == 0) {
        out[b * 4 + 0] = 1.f / (1.f + expf(-(a0 + __ldg(&b_bb[0]))));
        out[b * 4 + 1] = 1.f / (1.f + expf(-(a1 + __ldg(&b_bb[1]))));
        out[b * 4 + 2] = 1.f / (1.f + expf(-(a2 + __ldg(&b_bb[2]))));
        out[b * 4 + 3] = 1.f / (1.f + expf(-(a3 + __ldg(&b_bb[3]))));
    }
}

extern "C" void kernel_launch(void* const* d_in, const int* in_sizes, int n_in,
                              void* d_out, int out_size) {
    const float* x0    = (const float*)d_in[0];
    const float* flow  = (const float*)d_in[1];
    const float* h     = (const float*)d_in[2];
    const float* W_in  = (const float*)d_in[3];
    const float* W_x   = (const float*)d_in[4];
    const float* W_dt  = (const float*)d_in[5];
    const float* b_dt  = (const float*)d_in[6];
    const float* A_log = (const float*)d_in[7];
    const float* Dv    = (const float*)d_in[8];
    const float* W1    = (const float*)d_in[9];
    const float* b1    = (const float*)d_in[10];
    const float* W2    = (const float*)d_in[11];
    const float* b2    = (const float*)d_in[12];
    const float* gamma = (const float*)d_in[13];
    const float* beta  = (const float*)d_in[14];
    const float* W_bb  = (const float*)d_in[15];
    const float* b_bb  = (const float*)d_in[16];

    float* out   = (float*)d_out;                 // (B, 4)
    float* h_new = out + (size_t)BTOT * 4;        // (B, 256, 16)

    const int GSMEM = 2 * 32768 + 128;
    cudaFuncSetAttribute(k_hgemm<256, 512, 0>,
                         cudaFuncAttributeMaxDynamicSharedMemorySize, GSMEM);
    cudaFuncSetAttribute(k_hgemm<256, 512, 1>,
                         cudaFuncAttributeMaxDynamicSharedMemorySize, GSMEM);
    cudaFuncSetAttribute(k_hgemm<512, 256, 2>,
                         cudaFuncAttributeMaxDynamicSharedMemorySize, GSMEM);
    const int PGRID = 296;   // 148 SMs x 2 CTAs

    static cudaStream_t s1 = nullptr;
    static cudaEvent_t evFork = nullptr, evJoin = nullptr;
    if (s1 == nullptr) {
        cudaStreamCreateWithFlags(&s1, cudaStreamNonBlocking);
        cudaEventCreateWithFlags(&evFork, cudaEventDisableTiming);
        cudaEventCreateWithFlags(&evJoin, cudaEventDisableTiming);
    }

    // shared weight prep (serial, ~15us)
    k_prep<<<16, 256>>>(A_log);
    k_packw<<<512, 256>>>(W_in, 256, 0);
    k_packw<<<512, 256>>>(W1, 256, 1);
    k_packw<<<512, 256>>>(W2, 512, 2);
    cudaEventRecord(evFork, 0);
    cudaStreamWaitEvent(s1, evFork, 0);

    // ---- half 0 on main stream ----
    k_embed<<<BHALF, 256>>>(x0, 0);
    k_xdbl<<<dim3(BHALF / 16, 3), 256>>>(flow, W_x, W_dt, b_dt, 0);
    k_hgemm<256, 512, 0><<<PGRID, 256, GSMEM>>>((const float*)nullptr, 0);
    k_mamba<<<BHALF, 256>>>(h, Dv, h_new, 0);
    k_hgemm<256, 512, 1><<<PGRID, 256, GSMEM>>>(b1, 0);
    k_hgemm<512, 256, 2><<<PGRID, 256, GSMEM>>>(b2, 0);
    k_head<<<BHALF / 8, 256>>>(gamma, beta, W_bb, b_bb, out, 0);

    // ---- half 1 on side stream ----
    k_embed<<<BHALF, 256, 0, s1>>>(x0, BHALF);
    k_xdbl<<<dim3(BHALF / 16, 3), 256, 0, s1>>>(flow, W_x, W_dt, b_dt, BHALF);
    k_hgemm<256, 512, 0><<<PGRID, 256, GSMEM, s1>>>((const float*)nullptr, BHALF);
    k_mamba<<<BHALF, 256, 0, s1>>>(h, Dv, h_new, BHALF);
    k_hgemm<256, 512, 1><<<PGRID, 256, GSMEM, s1>>>(b1, BHALF);
    k_hgemm<512, 256, 2><<<PGRID, 256, GSMEM, s1>>>(b2, BHALF);
    k_head<<<BHALF / 8, 256, 0, s1>>>(gamma, beta, W_bb, b_bb, out, BHALF);

    cudaEventRecord(evJoin, s1);
    cudaStreamWaitEvent(0, evJoin, 0);
}